// round 2
// baseline (speedup 1.0000x reference)
#include <cuda_runtime.h>
#include <math.h>

// ---------------------------------------------------------------------------
// Problem constants
// ---------------------------------------------------------------------------
#define NB   64
#define CIN  3
#define TT   300
#define VV   25
#define EMB  96
#define OUTC 96
#define WIN  5
#define TV   (TT*VV)          // 7500
#define TVP  ((TT+4)*VV)      // 7600  (B buffer padded +/-2 frames)

// ---------------------------------------------------------------------------
// Device-global scratch (module-static; no runtime allocation)
// ---------------------------------------------------------------------------
__device__ float g_Nmat[5][25][25];     // normalized 25x25 hop matrices, s=1..5
__device__ float g_W2[96][15];          // inv_e * mlp_w[e, (s+1)*3+c], s=0..4
__device__ float g_coef2[96][3][25];    // B-path coefficients (inv folded)
__device__ float g_cb[96];              // folded mlp bias+BN
__device__ float g_OW2[5][96][96];      // [w][e][o] = inv2_o * out_w[o][e][w]
__device__ float g_ob[96];              // folded out bias+BN
__device__ float g_A[NB][EMB][TV];      // w-independent part of h
__device__ float g_B[NB][EMB][TVP];     // w-dependent part, frame-padded by 2

// ---------------------------------------------------------------------------
// f32x2 helpers (sm_103a packed fp32)
// ---------------------------------------------------------------------------
__device__ __forceinline__ unsigned long long pack2(float a, float b) {
    unsigned long long r;
    asm("mov.b64 %0, {%1, %2};" : "=l"(r) : "f"(a), "f"(b));
    return r;
}
__device__ __forceinline__ void unpack2(unsigned long long v, float& lo, float& hi) {
    asm("mov.b64 {%0, %1}, %2;" : "=f"(lo), "=f"(hi) : "l"(v));
}
__device__ __forceinline__ void fma2(unsigned long long& acc,
                                     unsigned long long a, unsigned long long b) {
    asm("fma.rn.f32x2 %0, %1, %2, %0;" : "+l"(acc) : "l"(a), "l"(b));
}

// ---------------------------------------------------------------------------
// Setup kernel: graph hop masks, normalization, BN folding. One block.
// ---------------------------------------------------------------------------
__global__ void kSetup(const float* __restrict__ mlp_w, const float* __restrict__ mlp_b,
                       const float* __restrict__ g1, const float* __restrict__ b1,
                       const float* __restrict__ m1, const float* __restrict__ v1,
                       const float* __restrict__ out_w, const float* __restrict__ out_b,
                       const float* __restrict__ g2, const float* __restrict__ b2,
                       const float* __restrict__ m2, const float* __restrict__ v2)
{
    __shared__ unsigned char S[6][25][25];   // S[k] = supp((A+I)^k), k=1..5
    __shared__ double alpha[6][25];
    __shared__ double alpha2[6][25];
    int tid = threadIdx.x;

    if (tid == 0) {
        const int eg[24][2] = {{1,2},{2,21},{3,21},{4,3},{5,21},{6,5},{7,6},{8,7},
                               {9,21},{10,9},{11,10},{12,11},{13,1},{14,13},{15,14},
                               {16,15},{17,1},{18,17},{19,18},{20,19},{22,23},{23,8},
                               {24,25},{25,12}};
        unsigned char Bm[25][25];
        for (int i = 0; i < 25; i++)
            for (int j = 0; j < 25; j++) Bm[i][j] = (i == j);
        for (int k = 0; k < 24; k++) {
            int a = eg[k][0] - 1, b = eg[k][1] - 1;
            Bm[a][b] = 1; Bm[b][a] = 1;
        }
        for (int i = 0; i < 25; i++)
            for (int j = 0; j < 25; j++) S[1][i][j] = Bm[i][j];
        for (int k = 2; k <= 5; k++)
            for (int i = 0; i < 25; i++)
                for (int j = 0; j < 25; j++) {
                    unsigned char r = 0;
                    for (int l = 0; l < 25; l++) r |= (unsigned char)(S[k-1][i][l] & Bm[l][j]);
                    S[k][i][j] = r;
                }
        for (int s = 1; s <= 5; s++)
            for (int v = 0; v < 25; v++) {
                int r = 0;
                for (int u = 0; u < 25; u++) {
                    int d = (s == 1) ? (int)S[1][v][u] : ((int)S[s][v][u] - (int)S[s-1][v][u]);
                    r += d;
                }
                int deg = 5 * r + ((s == 1) ? 0 : 1);
                double a = (deg > 0) ? 1.0 / sqrt((double)deg) : 0.0;
                alpha[s][v] = a;
                alpha2[s][v] = a * a;
            }
    }
    __syncthreads();

    for (int i = tid; i < 5 * 625; i += blockDim.x) {
        int s = i / 625 + 1, v = (i / 25) % 25, u = i % 25;
        int d = (s == 1) ? (int)S[1][v][u] : ((int)S[s][v][u] - (int)S[s-1][v][u]);
        g_Nmat[s-1][v][u] = d ? (float)(alpha[s][v] * alpha[s][u]) : 0.f;
    }
    for (int e = tid; e < 96; e += blockDim.x) {
        float inv = g1[e] / sqrtf(v1[e] + 1e-5f);
        g_cb[e] = mlp_b[e] * inv + b1[e] - m1[e] * inv;
        for (int s = 0; s < 5; s++)
            for (int c = 0; c < 3; c++)
                g_W2[e][s*3+c] = inv * mlp_w[e*18 + (s+1)*3 + c];
        for (int c = 0; c < 3; c++)
            for (int v = 0; v < 25; v++) {
                float acc = mlp_w[e*18 + c];                    // s=0 (identity scale)
                for (int s = 2; s <= 5; s++)
                    acc += (float)alpha2[s][v] * mlp_w[e*18 + s*3 + c];
                g_coef2[e][c][v] = inv * acc;
            }
        // e doubles as output channel o below
        float inv2 = g2[e] / sqrtf(v2[e] + 1e-5f);
        g_ob[e] = out_b[e] * inv2 + b2[e] - m2[e] * inv2;
        for (int q = 0; q < 96; q++)
            for (int w = 0; w < 5; w++)
                g_OW2[w][q][e] = inv2 * out_w[(e*96 + q)*5 + w];
    }
}

// ---------------------------------------------------------------------------
// A/B producer kernel: one block per (frame f, batch n). 128 threads.
//   t = f-2: A[n,:,t,:] (window-sum + 25x25 matvecs + 15-term mix)
//            B[n,:,f,:] (3-term per-joint mix); pad frames -> zeros.
// ---------------------------------------------------------------------------
__global__ __launch_bounds__(128) void kAB(const float* __restrict__ x)
{
    int f = blockIdx.x;           // 0..303
    int n = blockIdx.y;
    int t = f - 2;
    int tid = threadIdx.x;

    if (t < 0 || t >= TT) {       // pad frames of B buffer
        for (int i = tid; i < EMB * VV; i += 128) {
            int e = i / VV, v = i % VV;
            g_B[n][e][f*VV + v] = 0.f;
        }
        return;
    }

    __shared__ float Xs[3][25];
    __shared__ float xt[3][25];
    __shared__ float ms[15][25];
    __shared__ float W2s[96][15];

    if (tid < 75) {
        int c = tid / 25, u = tid % 25;
        float s = 0.f;
        #pragma unroll
        for (int w = 0; w < 5; w++) {
            int tau = t + w - 2;
            if (tau >= 0 && tau < TT) s += x[((n*3 + c)*TT + tau)*VV + u];
        }
        Xs[c][u] = s;
        xt[c][u] = x[((n*3 + c)*TT + t)*VV + u];
    }
    for (int i = tid; i < 96*15; i += 128)
        W2s[i/15][i%15] = (&g_W2[0][0])[i];
    __syncthreads();

    for (int i = tid; i < 375; i += 128) {
        int sc = i / 25, v = i % 25;
        int s = sc / 3, c = sc % 3;
        float acc = 0.f;
        const float* Nrow = &g_Nmat[s][v][0];
        const float* Xr = &Xs[c][0];
        #pragma unroll
        for (int u = 0; u < 25; u++) acc += Nrow[u] * Xr[u];
        ms[sc][v] = acc;
    }
    __syncthreads();

    for (int i = tid; i < EMB*VV; i += 128) {
        int e = i / VV, v = i % VV;
        float a = 0.f;
        #pragma unroll
        for (int sc = 0; sc < 15; sc++) a += W2s[e][sc] * ms[sc][v];
        g_A[n][e][t*VV + v] = a;
        float b = 0.f;
        #pragma unroll
        for (int c = 0; c < 3; c++) b += g_coef2[e][c][v] * xt[c][v];
        g_B[n][e][f*VV + v] = b;
    }
}

// ---------------------------------------------------------------------------
// Output GEMM: out[n,o,tv] = ob[o] + sum_{w,e} OW2[w][e][o]*relu(A+B_shift+cb)
// Block: 96 o x 128 cols, 256 threads (8 o-groups x 32 col-groups),
// thread tile 12 o x 4 cols via f32x2 (o-pairs).
// ---------------------------------------------------------------------------
__global__ __launch_bounds__(256, 2) void kOut(float* __restrict__ out)
{
    extern __shared__ float sm[];
    float* Hs  = sm;                   // [96][128]
    float* OWs = sm + 96*128;          // [96][96] for current w
    float* cbs = OWs + 96*96;          // [96]
    float* obs = cbs + 96;             // [96]

    int tid = threadIdx.x;
    int n = blockIdx.y;
    int col0 = blockIdx.x * 128;

    if (tid < 96) { cbs[tid] = g_cb[tid]; obs[tid] = g_ob[tid]; }
    __syncthreads();

    int og = tid >> 5;      // 0..7
    int cg = tid & 31;      // 0..31

    unsigned long long acc[6][4];
    #pragma unroll
    for (int p = 0; p < 6; p++)
        #pragma unroll
        for (int j = 0; j < 4; j++) acc[p][j] = 0ULL;

    const float* Arow = &g_A[n][0][0];
    const float* Brow = &g_B[n][0][0];

    for (int w = 0; w < 5; w++) {
        // stage OW chunk for this w
        const float4* src = (const float4*)&g_OW2[w][0][0];
        float4* dst = (float4*)OWs;
        for (int i = tid; i < (96*96)/4; i += 256) dst[i] = src[i];
        // build H chunk
        int boff = w * 25;
        for (int i = tid; i < 96*128; i += 256) {
            int e = i >> 7, col = i & 127;
            int tv = col0 + col;
            float h = 0.f;
            if (tv < TV) {
                float a = Arow[e*TV + tv];
                float b = Brow[e*TVP + tv + boff];
                h = fmaxf(a + b + cbs[e], 0.f);
            }
            Hs[i] = h;
        }
        __syncthreads();

        #pragma unroll 2
        for (int e = 0; e < 96; e++) {
            float4 h4 = *(const float4*)(Hs + (e << 7) + (cg << 2));
            unsigned long long hh0 = pack2(h4.x, h4.x);
            unsigned long long hh1 = pack2(h4.y, h4.y);
            unsigned long long hh2 = pack2(h4.z, h4.z);
            unsigned long long hh3 = pack2(h4.w, h4.w);
            const unsigned long long* wp =
                (const unsigned long long*)(OWs + e*96 + og*12);
            #pragma unroll
            for (int p = 0; p < 6; p++) {
                unsigned long long w2 = wp[p];
                fma2(acc[p][0], w2, hh0);
                fma2(acc[p][1], w2, hh1);
                fma2(acc[p][2], w2, hh2);
                fma2(acc[p][3], w2, hh3);
            }
        }
        __syncthreads();
    }

    // epilogue
    int tvb = col0 + (cg << 2);
    if (tvb < TV) {
        #pragma unroll
        for (int p = 0; p < 6; p++) {
            int o = og*12 + p*2;
            float blo = obs[o], bhi = obs[o+1];
            float l0,h0,l1,h1,l2,h2,l3,h3;
            unpack2(acc[p][0], l0, h0);
            unpack2(acc[p][1], l1, h1);
            unpack2(acc[p][2], l2, h2);
            unpack2(acc[p][3], l3, h3);
            float4 vlo = make_float4(l0+blo, l1+blo, l2+blo, l3+blo);
            float4 vhi = make_float4(h0+bhi, h1+bhi, h2+bhi, h3+bhi);
            *(float4*)&out[((size_t)(n*96 + o))*TV + tvb]     = vlo;
            *(float4*)&out[((size_t)(n*96 + o + 1))*TV + tvb] = vhi;
        }
    }
}

// ---------------------------------------------------------------------------
// Launcher
// ---------------------------------------------------------------------------
extern "C" void kernel_launch(void* const* d_in, const int* in_sizes, int n_in,
                              void* d_out, int out_size)
{
    (void)in_sizes; (void)n_in; (void)out_size;
    const float* x     = (const float*)d_in[0];
    const float* mlp_w = (const float*)d_in[1];
    const float* mlp_b = (const float*)d_in[2];
    const float* g1    = (const float*)d_in[3];
    const float* b1    = (const float*)d_in[4];
    const float* m1    = (const float*)d_in[5];
    const float* v1    = (const float*)d_in[6];
    const float* out_w = (const float*)d_in[7];
    const float* out_b = (const float*)d_in[8];
    const float* g2    = (const float*)d_in[9];
    const float* b2    = (const float*)d_in[10];
    const float* m2    = (const float*)d_in[11];
    const float* v2    = (const float*)d_in[12];
    float* out = (float*)d_out;

    const int smem3 = (96*128 + 96*96 + 192) * (int)sizeof(float);  // 86784 B
    cudaFuncSetAttribute(kOut, cudaFuncAttributeMaxDynamicSharedMemorySize, smem3);

    kSetup<<<1, 256>>>(mlp_w, mlp_b, g1, b1, m1, v1, out_w, out_b, g2, b2, m2, v2);
    kAB<<<dim3(TT + 4, NB), 128>>>(x);
    kOut<<<dim3((TV + 127) / 128, NB), 256, smem3>>>(out);
}

// round 4
// speedup vs baseline: 1.7297x; 1.7297x over previous
#include <cuda_runtime.h>
#include <math.h>

// ---------------------------------------------------------------------------
// Problem constants
// ---------------------------------------------------------------------------
#define NB   64
#define CIN  3
#define TT   300
#define VV   25
#define EMB  96
#define OUTC 96
#define WIN  5
#define TV   (TT*VV)          // 7500
#define TVP  ((TT+4)*VV)      // 7600  (B buffer padded +/-2 frames)

// ---------------------------------------------------------------------------
// Device-global scratch (module-static; no runtime allocation)
// ---------------------------------------------------------------------------
__device__ float g_Nmat[5][25][25];     // normalized 25x25 hop matrices, s=1..5
__device__ float g_W2[96][15];          // inv_e * mlp_w[e, (s+1)*3+c], s=0..4
__device__ float g_coef2[96][3][25];    // B-path coefficients (inv folded)
__device__ float g_cb[96];              // folded mlp bias+BN
__device__ float g_OW2[5][96][96];      // [w][e][o] = inv2_o * out_w[o][e][w]
__device__ float g_ob[96];              // folded out bias+BN
__device__ float g_A[NB][EMB][TV];      // w-independent part of h, +cb folded in
__device__ float g_B[NB][EMB][TVP];     // w-dependent part, frame-padded by 2

// ---------------------------------------------------------------------------
// f32x2 helpers (sm_103a packed fp32)
// ---------------------------------------------------------------------------
__device__ __forceinline__ unsigned long long pack2(float a, float b) {
    unsigned long long r;
    asm("mov.b64 %0, {%1, %2};" : "=l"(r) : "f"(a), "f"(b));
    return r;
}
__device__ __forceinline__ void unpack2(unsigned long long v, float& lo, float& hi) {
    asm("mov.b64 {%0, %1}, %2;" : "=f"(lo), "=f"(hi) : "l"(v));
}
__device__ __forceinline__ void fma2(unsigned long long& acc,
                                     unsigned long long a, unsigned long long b) {
    asm("fma.rn.f32x2 %0, %1, %2, %0;" : "+l"(acc) : "l"(a), "l"(b));
}

// ---------------------------------------------------------------------------
// Setup kernel: bitmask hop masks, normalization, BN folding. One block, fp32.
// ---------------------------------------------------------------------------
__global__ __launch_bounds__(256) void kSetup(
                       const float* __restrict__ mlp_w, const float* __restrict__ mlp_b,
                       const float* __restrict__ g1, const float* __restrict__ b1,
                       const float* __restrict__ m1, const float* __restrict__ v1,
                       const float* __restrict__ out_w, const float* __restrict__ out_b,
                       const float* __restrict__ g2, const float* __restrict__ b2,
                       const float* __restrict__ m2, const float* __restrict__ v2)
{
    __shared__ unsigned int Brow[25];    // adjacency(+I) rows as bitmasks
    __shared__ unsigned int Sm[6][25];   // S_k = supp((A+I)^k) rows
    __shared__ float alph[6][25];
    __shared__ float alph2[6][25];
    __shared__ float inv1s[96], inv2s[96];
    int tid = threadIdx.x;

    if (tid < 25) {
        const unsigned char eg[24][2] = {{1,2},{2,21},{3,21},{4,3},{5,21},{6,5},
            {7,6},{8,7},{9,21},{10,9},{11,10},{12,11},{13,1},{14,13},{15,14},
            {16,15},{17,1},{18,17},{19,18},{20,19},{22,23},{23,8},{24,25},{25,12}};
        unsigned int m = 1u << tid;
        #pragma unroll
        for (int k = 0; k < 24; k++) {
            int a = eg[k][0] - 1, b = eg[k][1] - 1;
            if (a == tid) m |= 1u << b;
            if (b == tid) m |= 1u << a;
        }
        Brow[tid] = m;
        Sm[0][tid] = 1u << tid;
        Sm[1][tid] = m;
    }
    if (tid < 96) {
        inv1s[tid] = g1[tid] / sqrtf(v1[tid] + 1e-5f);
        inv2s[tid] = g2[tid] / sqrtf(v2[tid] + 1e-5f);
    }
    __syncthreads();

    for (int k = 2; k <= 5; k++) {
        if (tid < 25) {
            unsigned int prev = Sm[k-1][tid], nm = prev;
            for (int u = 0; u < 25; u++)
                if ((prev >> u) & 1) nm |= Brow[u];
            Sm[k][tid] = nm;
        }
        __syncthreads();
    }

    if (tid < 125) {
        int s = tid / 25 + 1, v = tid % 25;
        int r = __popc(Sm[s][v]) - ((s >= 2) ? __popc(Sm[s-1][v]) : 0);
        int deg = 5 * r + ((s == 1) ? 0 : 1);
        alph[s][v]  = (deg > 0) ? 1.0f / sqrtf((float)deg) : 0.f;
        alph2[s][v] = (deg > 0) ? 1.0f / (float)deg : 0.f;
    }
    __syncthreads();

    // normalized hop matrices
    for (int i = tid; i < 3125; i += 256) {
        int s = i / 625 + 1, v = (i / 25) % 25, u = i % 25;
        unsigned int bits = Sm[s][v] & ~((s >= 2) ? Sm[s-1][v] : 0u);
        g_Nmat[s-1][v][u] = ((bits >> u) & 1) ? alph[s][v] * alph[s][u] : 0.f;
    }
    // W2 (scales 1..5, BN folded)
    for (int i = tid; i < 96 * 15; i += 256) {
        int e = i / 15, sc = i % 15;
        int s = sc / 3, c = sc % 3;
        g_W2[e][sc] = inv1s[e] * mlp_w[e*18 + (s+1)*3 + c];
    }
    if (tid < 96) {
        g_cb[tid] = mlp_b[tid] * inv1s[tid] + b1[tid] - m1[tid] * inv1s[tid];
        g_ob[tid] = out_b[tid] * inv2s[tid] + b2[tid] - m2[tid] * inv2s[tid];
    }
    // B-path coefficients
    for (int i = tid; i < 7200; i += 256) {
        int e = i / 75, c = (i / 25) % 3, v = i % 25;
        float acc = mlp_w[e*18 + c];
        #pragma unroll
        for (int s = 2; s <= 5; s++)
            acc += alph2[s][v] * mlp_w[e*18 + s*3 + c];
        g_coef2[e][c][v] = inv1s[e] * acc;
    }
    // output weights transposed, BN folded
    for (int i = tid; i < 96 * 96 * 5; i += 256) {
        int o = i / 480, q = (i / 5) % 96, w = i % 5;
        g_OW2[w][q][o] = inv2s[o] * out_w[i];
    }
}

// ---------------------------------------------------------------------------
// A/B producer: one block per (n, 4 frames) => 100 columns.
// A-part: register-blocked f32x2 GEMM  W2T[15x96] @ ms[15x100]  (+cb folded).
// B-part: (e,v)-pair sweep, 3-term mix reused over 4 frames.
// NOTE: all shared arrays that are vector-accessed carry __align__(16) —
// static __shared__ float arrays are otherwise only 4-byte aligned and
// LD.128 from them traps (round-3 failure).
// ---------------------------------------------------------------------------
__global__ __launch_bounds__(256) void kAB(const float* __restrict__ x)
{
    __shared__ __align__(16) float Ns[3125];     // hop matrices (flat [s][v][u])
    __shared__ __align__(16) float W2T[15][96];  // transposed mlp weights
    __shared__ __align__(16) float msS[15][104]; // graph-mixed window sums
    __shared__ __align__(16) float Xs[3][100];   // window sums per (c, col)
    __shared__ __align__(16) float xts[3][100];  // raw x per (c, col)
    __shared__ __align__(16) float cbs[96];

    int n  = blockIdx.y;
    int f0 = blockIdx.x * 4;          // B frames f0..f0+3
    int tb = f0 - 2;                  // A frames (t) tb..tb+3
    int tid = threadIdx.x;

    // stage constants
    for (int i = tid; i < 3125; i += 256) Ns[i] = ((const float*)g_Nmat)[i];
    for (int i = tid; i < 96 * 15; i += 256)
        W2T[i % 15][i / 15] = g_W2[i / 15][i % 15];
    if (tid < 96) cbs[tid] = g_cb[tid];

    // stage x window-sums and raw frames
    for (int i = tid; i < 300; i += 256) {
        int c = i / 100, col = i % 100;
        int t = tb + col / 25, v = col % 25;
        float xv = 0.f, s = 0.f;
        if (t >= 0 && t < TT) {
            const float* xp = &x[((n*3 + c)*TT + t)*VV + v];
            xv = xp[0];
            s = xv;
            if (t - 2 >= 0)  s += xp[-2*VV];
            if (t - 1 >= 0)  s += xp[-VV];
            if (t + 1 < TT)  s += xp[VV];
            if (t + 2 < TT)  s += xp[2*VV];
        }
        Xs[c][col] = s;
        xts[c][col] = xv;
    }
    __syncthreads();

    // ms[sc][col] = sum_u N_s[v][u] * Xsum_c[t][u]
    for (int i = tid; i < 1500; i += 256) {
        int sc = i / 100, col = i % 100;
        int s = sc / 3, c = sc % 3;
        int j = col / 25, v = col % 25;
        const float* Nrow = &Ns[(s*25 + v)*25];
        const float* Xr = &Xs[c][j*25];
        float acc = 0.f;
        #pragma unroll
        for (int u = 0; u < 25; u++) acc += Nrow[u] * Xr[u];
        msS[sc][col] = acc;
    }
    __syncthreads();

    // ---- A GEMM: thread tile 12 o (6 pairs) x 4 cols ----
    int og = tid >> 5;        // 0..7
    int cg = tid & 31;        // 0..31 (cg<25 active: 25*4 = 100 cols)
    if (cg < 25) {
        unsigned long long acc[6][4];
        #pragma unroll
        for (int p = 0; p < 6; p++)
            #pragma unroll
            for (int j = 0; j < 4; j++) acc[p][j] = 0ULL;

        #pragma unroll
        for (int sc = 0; sc < 15; sc++) {
            float4 m4 = *(const float4*)&msS[sc][cg << 2];
            unsigned long long hh0 = pack2(m4.x, m4.x);
            unsigned long long hh1 = pack2(m4.y, m4.y);
            unsigned long long hh2 = pack2(m4.z, m4.z);
            unsigned long long hh3 = pack2(m4.w, m4.w);
            const ulonglong2* wp = (const ulonglong2*)&W2T[sc][og * 12];
            ulonglong2 wa = wp[0], wb = wp[1], wc = wp[2];
            fma2(acc[0][0], wa.x, hh0); fma2(acc[0][1], wa.x, hh1);
            fma2(acc[0][2], wa.x, hh2); fma2(acc[0][3], wa.x, hh3);
            fma2(acc[1][0], wa.y, hh0); fma2(acc[1][1], wa.y, hh1);
            fma2(acc[1][2], wa.y, hh2); fma2(acc[1][3], wa.y, hh3);
            fma2(acc[2][0], wb.x, hh0); fma2(acc[2][1], wb.x, hh1);
            fma2(acc[2][2], wb.x, hh2); fma2(acc[2][3], wb.x, hh3);
            fma2(acc[3][0], wb.y, hh0); fma2(acc[3][1], wb.y, hh1);
            fma2(acc[3][2], wb.y, hh2); fma2(acc[3][3], wb.y, hh3);
            fma2(acc[4][0], wc.x, hh0); fma2(acc[4][1], wc.x, hh1);
            fma2(acc[4][2], wc.x, hh2); fma2(acc[4][3], wc.x, hh3);
            fma2(acc[5][0], wc.y, hh0); fma2(acc[5][1], wc.y, hh1);
            fma2(acc[5][2], wc.y, hh2); fma2(acc[5][3], wc.y, hh3);
        }

        // epilogue: +cb, write valid t range
        int colb = cg << 2;
        int lo = (tb < 0) ? -tb * 25 : 0;
        int hi = (300 - tb) * 25; if (hi > 100) hi = 100;
        long baseoff = (long)tb * VV;
        #pragma unroll
        for (int p = 0; p < 6; p++) {
            int o = og * 12 + 2 * p;
            float blo = cbs[o], bhi = cbs[o + 1];
            float vl[4], vh[4];
            #pragma unroll
            for (int j = 0; j < 4; j++) {
                float a, b; unpack2(acc[p][j], a, b);
                vl[j] = a + blo; vh[j] = b + bhi;
            }
            float* Ao = &g_A[n][o][0];
            float* Ao1 = &g_A[n][o + 1][0];
            #pragma unroll
            for (int k = 0; k < 4; k++) {
                int col = colb + k;
                if (col >= lo && col < hi) {
                    Ao[baseoff + col]  = vl[k];
                    Ao1[baseoff + col] = vh[k];
                }
            }
        }
    }

    // ---- B: per (e,v) pair, 4 frames ----
    for (int i = tid; i < 2400; i += 256) {
        int e = i / 25, v = i % 25;
        float c0 = g_coef2[e][0][v];
        float c1 = g_coef2[e][1][v];
        float c2 = g_coef2[e][2][v];
        float* Bo = &g_B[n][e][f0 * VV + v];
        #pragma unroll
        for (int j = 0; j < 4; j++) {
            int col = j * 25 + v;
            int t = tb + j;
            float b = c0 * xts[0][col] + c1 * xts[1][col] + c2 * xts[2][col];
            if (t < 0 || t >= TT) b = 0.f;
            Bo[j * VV] = b;
        }
    }
}

// ---------------------------------------------------------------------------
// Output GEMM: out[n,o,tv] = ob[o] + sum_{w,e} OW2[w][e][o]*relu(A'+B_shift)
// Block: 96 o x 128 cols, 256 threads, thread tile 12 o x 4 cols via f32x2.
// Dynamic smem base is 16-aligned; all internal offsets are multiples of 16B.
// ---------------------------------------------------------------------------
__global__ __launch_bounds__(256, 2) void kOut(float* __restrict__ out)
{
    extern __shared__ float sm[];
    float* Hs  = sm;                   // [96][128]
    float* OWs = sm + 96*128;          // [96][96] for current w
    float* obs = OWs + 96*96;          // [96]

    int tid = threadIdx.x;
    int n = blockIdx.y;
    int col0 = blockIdx.x * 128;

    if (tid < 96) obs[tid] = g_ob[tid];

    int og = tid >> 5;      // 0..7
    int cg = tid & 31;      // 0..31

    unsigned long long acc[6][4];
    #pragma unroll
    for (int p = 0; p < 6; p++)
        #pragma unroll
        for (int j = 0; j < 4; j++) acc[p][j] = 0ULL;

    const float* Arow = &g_A[n][0][0];
    const float* Brow = &g_B[n][0][0];
    bool interior = (col0 + 128 <= TV);

    for (int w = 0; w < 5; w++) {
        // stage OW chunk for this w
        const float4* src = (const float4*)&g_OW2[w][0][0];
        float4* dst = (float4*)OWs;
        for (int i = tid; i < (96*96)/4; i += 256) dst[i] = src[i];
        // build H chunk (vectorized on A side)
        int boff = w * 25;
        if (interior) {
            for (int q = tid; q < 96 * 32; q += 256) {
                int e = q >> 5, c4 = (q & 31) << 2;
                int tv = col0 + c4;
                float4 a4 = *(const float4*)(Arow + e*TV + tv);
                const float* bp = Brow + e*TVP + tv + boff;
                float4 h4;
                h4.x = fmaxf(a4.x + bp[0], 0.f);
                h4.y = fmaxf(a4.y + bp[1], 0.f);
                h4.z = fmaxf(a4.z + bp[2], 0.f);
                h4.w = fmaxf(a4.w + bp[3], 0.f);
                *(float4*)(Hs + (e << 7) + c4) = h4;
            }
        } else {
            for (int q = tid; q < 96 * 32; q += 256) {
                int e = q >> 5, c4 = (q & 31) << 2;
                int tv = col0 + c4;
                float4 h4;
                if (tv < TV) {   // TV%4==0: whole quad valid or invalid
                    float4 a4 = *(const float4*)(Arow + e*TV + tv);
                    const float* bp = Brow + e*TVP + tv + boff;
                    h4.x = fmaxf(a4.x + bp[0], 0.f);
                    h4.y = fmaxf(a4.y + bp[1], 0.f);
                    h4.z = fmaxf(a4.z + bp[2], 0.f);
                    h4.w = fmaxf(a4.w + bp[3], 0.f);
                } else {
                    h4 = make_float4(0.f, 0.f, 0.f, 0.f);
                }
                *(float4*)(Hs + (e << 7) + c4) = h4;
            }
        }
        __syncthreads();

        #pragma unroll 2
        for (int e = 0; e < 96; e++) {
            float4 h4 = *(const float4*)(Hs + (e << 7) + (cg << 2));
            unsigned long long hh0 = pack2(h4.x, h4.x);
            unsigned long long hh1 = pack2(h4.y, h4.y);
            unsigned long long hh2 = pack2(h4.z, h4.z);
            unsigned long long hh3 = pack2(h4.w, h4.w);
            const ulonglong2* wp = (const ulonglong2*)(OWs + e*96 + og*12);
            ulonglong2 wa = wp[0], wb = wp[1], wc = wp[2];
            fma2(acc[0][0], wa.x, hh0); fma2(acc[0][1], wa.x, hh1);
            fma2(acc[0][2], wa.x, hh2); fma2(acc[0][3], wa.x, hh3);
            fma2(acc[1][0], wa.y, hh0); fma2(acc[1][1], wa.y, hh1);
            fma2(acc[1][2], wa.y, hh2); fma2(acc[1][3], wa.y, hh3);
            fma2(acc[2][0], wb.x, hh0); fma2(acc[2][1], wb.x, hh1);
            fma2(acc[2][2], wb.x, hh2); fma2(acc[2][3], wb.x, hh3);
            fma2(acc[3][0], wb.y, hh0); fma2(acc[3][1], wb.y, hh1);
            fma2(acc[3][2], wb.y, hh2); fma2(acc[3][3], wb.y, hh3);
            fma2(acc[4][0], wc.x, hh0); fma2(acc[4][1], wc.x, hh1);
            fma2(acc[4][2], wc.x, hh2); fma2(acc[4][3], wc.x, hh3);
            fma2(acc[5][0], wc.y, hh0); fma2(acc[5][1], wc.y, hh1);
            fma2(acc[5][2], wc.y, hh2); fma2(acc[5][3], wc.y, hh3);
        }
        __syncthreads();
    }

    // epilogue
    int tvb = col0 + (cg << 2);
    if (tvb < TV) {
        #pragma unroll
        for (int p = 0; p < 6; p++) {
            int o = og*12 + p*2;
            float blo = obs[o], bhi = obs[o+1];
            float l0,h0,l1,h1,l2,h2,l3,h3;
            unpack2(acc[p][0], l0, h0);
            unpack2(acc[p][1], l1, h1);
            unpack2(acc[p][2], l2, h2);
            unpack2(acc[p][3], l3, h3);
            float4 vlo = make_float4(l0+blo, l1+blo, l2+blo, l3+blo);
            float4 vhi = make_float4(h0+bhi, h1+bhi, h2+bhi, h3+bhi);
            *(float4*)&out[((size_t)(n*96 + o))*TV + tvb]     = vlo;
            *(float4*)&out[((size_t)(n*96 + o + 1))*TV + tvb] = vhi;
        }
    }
}

// ---------------------------------------------------------------------------
// Launcher
// ---------------------------------------------------------------------------
extern "C" void kernel_launch(void* const* d_in, const int* in_sizes, int n_in,
                              void* d_out, int out_size)
{
    (void)in_sizes; (void)n_in; (void)out_size;
    const float* x     = (const float*)d_in[0];
    const float* mlp_w = (const float*)d_in[1];
    const float* mlp_b = (const float*)d_in[2];
    const float* g1    = (const float*)d_in[3];
    const float* b1    = (const float*)d_in[4];
    const float* m1    = (const float*)d_in[5];
    const float* v1    = (const float*)d_in[6];
    const float* out_w = (const float*)d_in[7];
    const float* out_b = (const float*)d_in[8];
    const float* g2    = (const float*)d_in[9];
    const float* b2    = (const float*)d_in[10];
    const float* m2    = (const float*)d_in[11];
    const float* v2    = (const float*)d_in[12];
    float* out = (float*)d_out;

    const int smem3 = (96*128 + 96*96 + 96) * (int)sizeof(float);  // 86400 B
    cudaFuncSetAttribute(kOut, cudaFuncAttributeMaxDynamicSharedMemorySize, smem3);

    kSetup<<<1, 256>>>(mlp_w, mlp_b, g1, b1, m1, v1, out_w, out_b, g2, b2, m2, v2);
    kAB<<<dim3(76, NB), 256>>>(x);
    kOut<<<dim3((TV + 127) / 128, NB), 256, smem3>>>(out);
}

// round 5
// speedup vs baseline: 1.8392x; 1.0633x over previous
#include <cuda_runtime.h>
#include <math.h>

// ---------------------------------------------------------------------------
// Problem constants
// ---------------------------------------------------------------------------
#define NB   64
#define TT   300
#define VV   25
#define PC   26                 // padded cols per frame (even => alignment)
#define EMB  96
#define TVA  (TT*PC)            // 7800  (A cols, padded)
#define NFB  (TT+4)             // 304   (B frames, +/-2 halo)
#define TVB  (NFB*PC)           // 7904
#define OUTTV (TT*VV)           // 7500  compact output cols

// ---------------------------------------------------------------------------
// Device-global scratch
// ---------------------------------------------------------------------------
__device__ __align__(16) float g_NmatF[3200];        // [s*625+v*25+u], zero-padded
__device__ __align__(16) float g_W2T[15][96];        // transposed mlp weights (BN folded)
__device__ __align__(16) float g_coef2[96][3][26];   // B coefs, v-padded (pad=0)
__device__ float g_cb[96];
__device__ __align__(16) float g_OW2[5][96][96];     // [w][e][o]
__device__ float g_ob[96];
__device__ __align__(16) float g_A[NB][EMB][TVA];    // A + cb, padded cols
__device__ __align__(16) float g_B[NB][EMB][TVB];    // B, frame-haloed, padded cols

// ---------------------------------------------------------------------------
// f32x2 helpers
// ---------------------------------------------------------------------------
__device__ __forceinline__ unsigned long long pack2(float a, float b) {
    unsigned long long r;
    asm("mov.b64 %0, {%1, %2};" : "=l"(r) : "f"(a), "f"(b));
    return r;
}
__device__ __forceinline__ void unpack2(unsigned long long v, float& lo, float& hi) {
    asm("mov.b64 {%0, %1}, %2;" : "=f"(lo), "=f"(hi) : "l"(v));
}
__device__ __forceinline__ void fma2(unsigned long long& acc,
                                     unsigned long long a, unsigned long long b) {
    asm("fma.rn.f32x2 %0, %1, %2, %0;" : "+l"(acc) : "l"(a), "l"(b));
}

// ---------------------------------------------------------------------------
// Setup: 8 blocks. Graph masks cheap (all blocks), heavy OW transform strided.
// ---------------------------------------------------------------------------
__global__ __launch_bounds__(256) void kSetup(
                       const float* __restrict__ mlp_w, const float* __restrict__ mlp_b,
                       const float* __restrict__ g1, const float* __restrict__ b1,
                       const float* __restrict__ m1, const float* __restrict__ v1,
                       const float* __restrict__ out_w, const float* __restrict__ out_b,
                       const float* __restrict__ g2, const float* __restrict__ b2,
                       const float* __restrict__ m2, const float* __restrict__ v2)
{
    __shared__ unsigned int Brow[25];
    __shared__ unsigned int Sm[6][25];
    __shared__ float alph[6][25];
    __shared__ float alph2[6][25];
    int tid = threadIdx.x;
    int bid = blockIdx.x;

    if (tid < 25) {
        const unsigned char eg[24][2] = {{1,2},{2,21},{3,21},{4,3},{5,21},{6,5},
            {7,6},{8,7},{9,21},{10,9},{11,10},{12,11},{13,1},{14,13},{15,14},
            {16,15},{17,1},{18,17},{19,18},{20,19},{22,23},{23,8},{24,25},{25,12}};
        unsigned int m = 1u << tid;
        #pragma unroll
        for (int k = 0; k < 24; k++) {
            int a = eg[k][0] - 1, b = eg[k][1] - 1;
            if (a == tid) m |= 1u << b;
            if (b == tid) m |= 1u << a;
        }
        Brow[tid] = m;
        Sm[1][tid] = m;
    }
    __syncthreads();
    for (int k = 2; k <= 5; k++) {
        if (tid < 25) {
            unsigned int prev = Sm[k-1][tid], nm = prev;
            for (int u = 0; u < 25; u++)
                if ((prev >> u) & 1) nm |= Brow[u];
            Sm[k][tid] = nm;
        }
        __syncthreads();
    }
    if (tid < 125) {
        int s = tid / 25 + 1, v = tid % 25;
        int r = __popc(Sm[s][v]) - ((s >= 2) ? __popc(Sm[s-1][v]) : 0);
        int deg = 5 * r + ((s == 1) ? 0 : 1);
        alph[s][v]  = (deg > 0) ? 1.0f / sqrtf((float)deg) : 0.f;
        alph2[s][v] = (deg > 0) ? 1.0f / (float)deg : 0.f;
    }
    __syncthreads();

    if (bid == 0) {
        for (int i = tid; i < 3200; i += 256) {
            float val = 0.f;
            if (i < 3125) {
                int s = i / 625 + 1, v = (i / 25) % 25, u = i % 25;
                unsigned int bits = Sm[s][v] & ~((s >= 2) ? Sm[s-1][v] : 0u);
                val = ((bits >> u) & 1) ? alph[s][v] * alph[s][u] : 0.f;
            }
            g_NmatF[i] = val;
        }
        for (int i = tid; i < 96 * 15; i += 256) {
            int e = i / 15, sc = i % 15;
            int s = sc / 3, c = sc % 3;
            float inv = g1[e] / sqrtf(v1[e] + 1e-5f);
            g_W2T[sc][e] = inv * mlp_w[e*18 + (s+1)*3 + c];
        }
        if (tid < 96) {
            float inv1 = g1[tid] / sqrtf(v1[tid] + 1e-5f);
            float inv2 = g2[tid] / sqrtf(v2[tid] + 1e-5f);
            g_cb[tid] = mlp_b[tid] * inv1 + b1[tid] - m1[tid] * inv1;
            g_ob[tid] = out_b[tid] * inv2 + b2[tid] - m2[tid] * inv2;
        }
        for (int i = tid; i < 96 * 3 * 26; i += 256) {
            int e = i / 78, c = (i / 26) % 3, v = i % 26;
            float val = 0.f;
            if (v < 25) {
                float acc = mlp_w[e*18 + c];
                #pragma unroll
                for (int s = 2; s <= 5; s++)
                    acc += alph2[s][v] * mlp_w[e*18 + s*3 + c];
                float inv = g1[e] / sqrtf(v1[e] + 1e-5f);
                val = inv * acc;
            }
            g_coef2[e][c][v] = val;
        }
    }
    // heavy part: spread across all 8 blocks
    for (int i = bid * 256 + tid; i < 96 * 96 * 5; i += 8 * 256) {
        int o = i / 480, q = (i / 5) % 96, w = i % 5;
        float inv2 = g2[o] / sqrtf(v2[o] + 1e-5f);
        g_OW2[w][q][o] = inv2 * out_w[i];
    }
}

// ---------------------------------------------------------------------------
// A/B producer: one block per (n, 8 B-frames). 256 threads.
// A: register-blocked f32x2 GEMM W2T[15x96] @ ms[15x208], two 104-col passes.
// B: f32x2 pair sweep (e, v-pair) x 8 frames.
// ---------------------------------------------------------------------------
__global__ __launch_bounds__(256) void kAB(const float* __restrict__ x)
{
    __shared__ __align__(16) float S[9416];
    float* NsS  = S;                // [3200]
    float* W2s  = S + 3200;         // [15][96]
    float* msS  = S + 4640;         // [15][208]
    float* XsS  = S + 7760;         // [3][8][26]
    float* xrS  = S + 8384;         // [3][12][26]
    float* cbs  = S + 9320;         // [96]

    int n  = blockIdx.y;
    int f0 = blockIdx.x * 8;        // B frames f0..f0+7
    int tid = threadIdx.x;

    // ---- stage constants + raw x ----
    {
        const float4* src = (const float4*)g_NmatF;
        float4* dst = (float4*)NsS;
        for (int i = tid; i < 800; i += 256) dst[i] = src[i];
        const float4* src2 = (const float4*)&g_W2T[0][0];
        float4* dst2 = (float4*)W2s;
        for (int i = tid; i < 360; i += 256) dst2[i] = src2[i];
    }
    if (tid < 96) cbs[tid] = g_cb[tid];
    for (int i = tid; i < 936; i += 256) {          // xr[c][fr][v], tau = f0-4+fr
        int c = i / 312, r = i - c * 312;
        int fr = r / 26, v = r - fr * 26;
        int tau = f0 - 4 + fr;
        float val = 0.f;
        if (tau >= 0 && tau < TT && v < 25)
            val = x[((n*3 + c)*TT + tau)*VV + v];
        xrS[i] = val;
    }
    __syncthreads();

    // ---- window sums: Xs[c][j][u], A-frame t = f0-2+j ----
    for (int i = tid; i < 624; i += 256) {
        int c = i / 208, r = i - c * 208;
        int j = r / 26, u = r - j * 26;
        const float* xp = &xrS[(c*12 + j)*26 + u];
        XsS[i] = xp[0] + xp[26] + xp[52] + xp[78] + xp[104];
    }
    __syncthreads();

    // ---- ms[sc][jj*26+v] = sum_u N_s[v][u] * Xs[c][jj][u] ----
    for (int i = tid; i < 3120; i += 256) {
        int sc = i / 208, col = i - sc * 208;
        int s = sc / 3, c = sc - s * 3;
        int j = col / 26, v = col - j * 26;
        const float* Nrow = &NsS[(s*25 + v)*25];
        const float* Xr = &XsS[(c*8 + j)*26];
        float acc = 0.f;
        #pragma unroll
        for (int u = 0; u < 25; u++) acc += Nrow[u] * Xr[u];
        msS[i] = acc;
    }
    __syncthreads();

    // ---- A GEMM: two passes of 104 cols; thread tile 12 o x 4 cols ----
    int og = tid >> 5;      // 0..7
    int cg = tid & 31;      // 0..31, active cg<26
    for (int h = 0; h < 2; h++) {
        if (cg < 26) {
            unsigned long long acc[6][4];
            #pragma unroll
            for (int p = 0; p < 6; p++)
                #pragma unroll
                for (int j = 0; j < 4; j++) acc[p][j] = 0ULL;

            int colb = cg << 2;
            #pragma unroll
            for (int sc = 0; sc < 15; sc++) {
                float4 m4 = *(const float4*)&msS[sc*208 + h*104 + colb];
                unsigned long long hh0 = pack2(m4.x, m4.x);
                unsigned long long hh1 = pack2(m4.y, m4.y);
                unsigned long long hh2 = pack2(m4.z, m4.z);
                unsigned long long hh3 = pack2(m4.w, m4.w);
                const ulonglong2* wp = (const ulonglong2*)&W2s[sc*96 + og*12];
                ulonglong2 wa = wp[0], wb = wp[1], wc = wp[2];
                fma2(acc[0][0], wa.x, hh0); fma2(acc[0][1], wa.x, hh1);
                fma2(acc[0][2], wa.x, hh2); fma2(acc[0][3], wa.x, hh3);
                fma2(acc[1][0], wa.y, hh0); fma2(acc[1][1], wa.y, hh1);
                fma2(acc[1][2], wa.y, hh2); fma2(acc[1][3], wa.y, hh3);
                fma2(acc[2][0], wb.x, hh0); fma2(acc[2][1], wb.x, hh1);
                fma2(acc[2][2], wb.x, hh2); fma2(acc[2][3], wb.x, hh3);
                fma2(acc[3][0], wb.y, hh0); fma2(acc[3][1], wb.y, hh1);
                fma2(acc[3][2], wb.y, hh2); fma2(acc[3][3], wb.y, hh3);
                fma2(acc[4][0], wc.x, hh0); fma2(acc[4][1], wc.x, hh1);
                fma2(acc[4][2], wc.x, hh2); fma2(acc[4][3], wc.x, hh3);
                fma2(acc[5][0], wc.y, hh0); fma2(acc[5][1], wc.y, hh1);
                fma2(acc[5][2], wc.y, hh2); fma2(acc[5][3], wc.y, hh3);
            }

            // epilogue: +cb, vector store into padded g_A
            int t0 = f0 - 2 + 4*h;                       // always even
            int lo = (t0 < 0) ? (-t0) * PC : 0;          // multiple of 4
            int hi = ((TT - t0) < 4 ? (TT - t0) : 4) * PC;
            if (colb >= lo && colb + 4 <= hi) {
                long gc = (long)t0 * PC + colb;
                #pragma unroll
                for (int p = 0; p < 6; p++) {
                    int o = og * 12 + 2 * p;
                    float blo = cbs[o], bhi = cbs[o + 1];
                    float l0,h0_,l1,h1_,l2,h2_,l3,h3_;
                    unpack2(acc[p][0], l0, h0_);
                    unpack2(acc[p][1], l1, h1_);
                    unpack2(acc[p][2], l2, h2_);
                    unpack2(acc[p][3], l3, h3_);
                    *(float4*)&g_A[n][o][gc] =
                        make_float4(l0+blo, l1+blo, l2+blo, l3+blo);
                    *(float4*)&g_A[n][o+1][gc] =
                        make_float4(h0_+bhi, h1_+bhi, h2_+bhi, h3_+bhi);
                }
            }
        }
    }

    // ---- B: (e, v-pair) x 8 frames, f32x2 ----
    for (int i = tid; i < 96 * 13; i += 256) {
        int e = i / 13, vp = i - e * 13;
        int v = vp << 1;
        float2 c0 = *(const float2*)&g_coef2[e][0][v];
        float2 c1 = *(const float2*)&g_coef2[e][1][v];
        float2 c2 = *(const float2*)&g_coef2[e][2][v];
        unsigned long long cc0 = pack2(c0.x, c0.y);
        unsigned long long cc1 = pack2(c1.x, c1.y);
        unsigned long long cc2 = pack2(c2.x, c2.y);
        float* Bo = &g_B[n][e][(long)f0 * PC + v];
        #pragma unroll
        for (int j = 0; j < 8; j++) {
            float2 x0 = *(const float2*)&xrS[((0*12) + j+2)*26 + v];
            float2 x1 = *(const float2*)&xrS[((1*12) + j+2)*26 + v];
            float2 x2 = *(const float2*)&xrS[((2*12) + j+2)*26 + v];
            unsigned long long acc = 0ULL;
            fma2(acc, cc0, pack2(x0.x, x0.y));
            fma2(acc, cc1, pack2(x1.x, x1.y));
            fma2(acc, cc2, pack2(x2.x, x2.y));
            float lo, hi;
            unpack2(acc, lo, hi);
            *(float2*)(Bo + j * PC) = make_float2(lo, hi);
        }
    }
}

// ---------------------------------------------------------------------------
// Output GEMM over padded cols: out = ob + sum_{w,e} OW2[w][e][:]*relu(A+Bsh)
// Block: 96 o x 128 padded cols, 256 threads, thread tile 12 o x 4 cols.
// ---------------------------------------------------------------------------
__global__ __launch_bounds__(256, 2) void kOut(float* __restrict__ out)
{
    extern __shared__ float sm[];
    float* Hs  = sm;                   // [96][128]
    float* OWs = sm + 96*128;          // [96][96]
    float* obs = OWs + 96*96;          // [96]

    int tid = threadIdx.x;
    int n = blockIdx.y;
    int col0 = blockIdx.x * 128;

    if (tid < 96) obs[tid] = g_ob[tid];

    int og = tid >> 5;
    int cg = tid & 31;

    unsigned long long acc[6][4];
    #pragma unroll
    for (int p = 0; p < 6; p++)
        #pragma unroll
        for (int j = 0; j < 4; j++) acc[p][j] = 0ULL;

    const float* Arow = &g_A[n][0][0];
    const float* Brow = &g_B[n][0][0];

    #pragma unroll
    for (int w = 0; w < 5; w++) {
        // stage OW chunk
        const float4* src = (const float4*)&g_OW2[w][0][0];
        float4* dst = (float4*)OWs;
        for (int i = tid; i < (96*96)/4; i += 256) dst[i] = src[i];
        // build H chunk: all-vector loads thanks to 26-padding
        for (int q = tid; q < 96 * 32; q += 256) {
            int e = q >> 5, c4 = (q & 31) << 2;
            int tv = col0 + c4;
            float4 h4;
            if (tv < TVA) {
                float4 a4 = *(const float4*)(Arow + e*TVA + tv);
                const float* bp = Brow + e*TVB + tv + PC*w;
                float4 b4;
                if ((w & 1) == 0) {
                    b4 = *(const float4*)bp;
                } else {
                    float2 blo = *(const float2*)bp;
                    float2 bhi = *(const float2*)(bp + 2);
                    b4 = make_float4(blo.x, blo.y, bhi.x, bhi.y);
                }
                h4.x = fmaxf(a4.x + b4.x, 0.f);
                h4.y = fmaxf(a4.y + b4.y, 0.f);
                h4.z = fmaxf(a4.z + b4.z, 0.f);
                h4.w = fmaxf(a4.w + b4.w, 0.f);
            } else {
                h4 = make_float4(0.f, 0.f, 0.f, 0.f);
            }
            *(float4*)(Hs + (e << 7) + c4) = h4;
        }
        __syncthreads();

        #pragma unroll 2
        for (int e = 0; e < 96; e++) {
            float4 h4 = *(const float4*)(Hs + (e << 7) + (cg << 2));
            unsigned long long hh0 = pack2(h4.x, h4.x);
            unsigned long long hh1 = pack2(h4.y, h4.y);
            unsigned long long hh2 = pack2(h4.z, h4.z);
            unsigned long long hh3 = pack2(h4.w, h4.w);
            const ulonglong2* wp = (const ulonglong2*)(OWs + e*96 + og*12);
            ulonglong2 wa = wp[0], wb = wp[1], wc = wp[2];
            fma2(acc[0][0], wa.x, hh0); fma2(acc[0][1], wa.x, hh1);
            fma2(acc[0][2], wa.x, hh2); fma2(acc[0][3], wa.x, hh3);
            fma2(acc[1][0], wa.y, hh0); fma2(acc[1][1], wa.y, hh1);
            fma2(acc[1][2], wa.y, hh2); fma2(acc[1][3], wa.y, hh3);
            fma2(acc[2][0], wb.x, hh0); fma2(acc[2][1], wb.x, hh1);
            fma2(acc[2][2], wb.x, hh2); fma2(acc[2][3], wb.x, hh3);
            fma2(acc[3][0], wb.y, hh0); fma2(acc[3][1], wb.y, hh1);
            fma2(acc[3][2], wb.y, hh2); fma2(acc[3][3], wb.y, hh3);
            fma2(acc[4][0], wc.x, hh0); fma2(acc[4][1], wc.x, hh1);
            fma2(acc[4][2], wc.x, hh2); fma2(acc[4][3], wc.x, hh3);
            fma2(acc[5][0], wc.y, hh0); fma2(acc[5][1], wc.y, hh1);
            fma2(acc[5][2], wc.y, hh2); fma2(acc[5][3], wc.y, hh3);
        }
        __syncthreads();
    }

    // epilogue: padded col -> compact (t,v) mapping, scalar guarded stores
    int tvb = col0 + (cg << 2);
    int tk[4], vk[4];
    bool ok[4];
    #pragma unroll
    for (int k = 0; k < 4; k++) {
        int c = tvb + k;
        int t = c / PC;
        int v = c - t * PC;
        tk[k] = t; vk[k] = v;
        ok[k] = (c < TVA) && (v < VV);
    }
    #pragma unroll
    for (int p = 0; p < 6; p++) {
        int o = og*12 + p*2;
        float blo = obs[o], bhi = obs[o+1];
        float l[4], hh[4];
        unpack2(acc[p][0], l[0], hh[0]);
        unpack2(acc[p][1], l[1], hh[1]);
        unpack2(acc[p][2], l[2], hh[2]);
        unpack2(acc[p][3], l[3], hh[3]);
        float* o0 = &out[((size_t)(n*96 + o))*OUTTV];
        float* o1 = &out[((size_t)(n*96 + o + 1))*OUTTV];
        #pragma unroll
        for (int k = 0; k < 4; k++) {
            if (ok[k]) {
                int idx = tk[k]*VV + vk[k];
                o0[idx] = l[k] + blo;
                o1[idx] = hh[k] + bhi;
            }
        }
    }
}

// ---------------------------------------------------------------------------
// Launcher
// ---------------------------------------------------------------------------
extern "C" void kernel_launch(void* const* d_in, const int* in_sizes, int n_in,
                              void* d_out, int out_size)
{
    (void)in_sizes; (void)n_in; (void)out_size;
    const float* x     = (const float*)d_in[0];
    const float* mlp_w = (const float*)d_in[1];
    const float* mlp_b = (const float*)d_in[2];
    const float* g1    = (const float*)d_in[3];
    const float* b1    = (const float*)d_in[4];
    const float* m1    = (const float*)d_in[5];
    const float* v1    = (const float*)d_in[6];
    const float* out_w = (const float*)d_in[7];
    const float* out_b = (const float*)d_in[8];
    const float* g2    = (const float*)d_in[9];
    const float* b2    = (const float*)d_in[10];
    const float* m2    = (const float*)d_in[11];
    const float* v2    = (const float*)d_in[12];
    float* out = (float*)d_out;

    const int smem3 = (96*128 + 96*96 + 96) * (int)sizeof(float);  // 86400 B
    cudaFuncSetAttribute(kOut, cudaFuncAttributeMaxDynamicSharedMemorySize, smem3);

    kSetup<<<8, 256>>>(mlp_w, mlp_b, g1, b1, m1, v1, out_w, out_b, g2, b2, m2, v2);
    kAB<<<dim3(NFB / 8, NB), 256>>>(x);                 // 38 x 64
    kOut<<<dim3((TVA + 127) / 128, NB), 256, smem3>>>(out);  // 61 x 64
}

// round 6
// speedup vs baseline: 1.8418x; 1.0015x over previous
#include <cuda_runtime.h>
#include <math.h>

// ---------------------------------------------------------------------------
// Problem constants
// ---------------------------------------------------------------------------
#define NB   64
#define TT   300
#define VV   25
#define PC   26                 // padded cols per frame (even => alignment)
#define EMB  96
#define TVA  (TT*PC)            // 7800  (A cols, padded)
#define NFB  (TT+4)             // 304   (B frames, +/-2 halo)
#define TVB  (NFB*PC)           // 7904
#define OUTTV (TT*VV)           // 7500  compact output cols

// ---------------------------------------------------------------------------
// Device-global scratch
// ---------------------------------------------------------------------------
__device__ __align__(16) float g_NmatF[3200];        // [s*625+v*25+u], zero-padded
__device__ __align__(16) float g_W2T[15][96];        // transposed mlp weights (BN folded)
__device__ __align__(16) float g_coef2[96][3][26];   // B coefs, v-padded (pad=0)
__device__ float g_cb[96];
__device__ __align__(16) float g_OW2[5][96][96];     // [w][e][o]
__device__ float g_ob[96];
__device__ __align__(16) float g_A[NB][EMB][TVA];    // A + cb, padded cols
__device__ __align__(16) float g_B[NB][EMB][TVB];    // B, frame-haloed, padded cols

// ---------------------------------------------------------------------------
// f32x2 helpers
// ---------------------------------------------------------------------------
__device__ __forceinline__ unsigned long long pack2(float a, float b) {
    unsigned long long r;
    asm("mov.b64 %0, {%1, %2};" : "=l"(r) : "f"(a), "f"(b));
    return r;
}
__device__ __forceinline__ void unpack2(unsigned long long v, float& lo, float& hi) {
    asm("mov.b64 {%0, %1}, %2;" : "=f"(lo), "=f"(hi) : "l"(v));
}
__device__ __forceinline__ void fma2(unsigned long long& acc,
                                     unsigned long long a, unsigned long long b) {
    asm("fma.rn.f32x2 %0, %1, %2, %0;" : "+l"(acc) : "l"(a), "l"(b));
}

// ---------------------------------------------------------------------------
// Setup: 8 blocks. Graph masks cheap (all blocks), heavy OW transform strided.
// ---------------------------------------------------------------------------
__global__ __launch_bounds__(256) void kSetup(
                       const float* __restrict__ mlp_w, const float* __restrict__ mlp_b,
                       const float* __restrict__ g1, const float* __restrict__ b1,
                       const float* __restrict__ m1, const float* __restrict__ v1,
                       const float* __restrict__ out_w, const float* __restrict__ out_b,
                       const float* __restrict__ g2, const float* __restrict__ b2,
                       const float* __restrict__ m2, const float* __restrict__ v2)
{
    __shared__ unsigned int Brow[25];
    __shared__ unsigned int Sm[6][25];
    __shared__ float alph[6][25];
    __shared__ float alph2[6][25];
    int tid = threadIdx.x;
    int bid = blockIdx.x;

    if (tid < 25) {
        const unsigned char eg[24][2] = {{1,2},{2,21},{3,21},{4,3},{5,21},{6,5},
            {7,6},{8,7},{9,21},{10,9},{11,10},{12,11},{13,1},{14,13},{15,14},
            {16,15},{17,1},{18,17},{19,18},{20,19},{22,23},{23,8},{24,25},{25,12}};
        unsigned int m = 1u << tid;
        #pragma unroll
        for (int k = 0; k < 24; k++) {
            int a = eg[k][0] - 1, b = eg[k][1] - 1;
            if (a == tid) m |= 1u << b;
            if (b == tid) m |= 1u << a;
        }
        Brow[tid] = m;
        Sm[1][tid] = m;
    }
    __syncthreads();
    for (int k = 2; k <= 5; k++) {
        if (tid < 25) {
            unsigned int prev = Sm[k-1][tid], nm = prev;
            for (int u = 0; u < 25; u++)
                if ((prev >> u) & 1) nm |= Brow[u];
            Sm[k][tid] = nm;
        }
        __syncthreads();
    }
    if (tid < 125) {
        int s = tid / 25 + 1, v = tid % 25;
        int r = __popc(Sm[s][v]) - ((s >= 2) ? __popc(Sm[s-1][v]) : 0);
        int deg = 5 * r + ((s == 1) ? 0 : 1);
        alph[s][v]  = (deg > 0) ? 1.0f / sqrtf((float)deg) : 0.f;
        alph2[s][v] = (deg > 0) ? 1.0f / (float)deg : 0.f;
    }
    __syncthreads();

    if (bid == 0) {
        for (int i = tid; i < 3200; i += 256) {
            float val = 0.f;
            if (i < 3125) {
                int s = i / 625 + 1, v = (i / 25) % 25, u = i % 25;
                unsigned int bits = Sm[s][v] & ~((s >= 2) ? Sm[s-1][v] : 0u);
                val = ((bits >> u) & 1) ? alph[s][v] * alph[s][u] : 0.f;
            }
            g_NmatF[i] = val;
        }
        for (int i = tid; i < 96 * 15; i += 256) {
            int e = i / 15, sc = i % 15;
            int s = sc / 3, c = sc % 3;
            float inv = g1[e] / sqrtf(v1[e] + 1e-5f);
            g_W2T[sc][e] = inv * mlp_w[e*18 + (s+1)*3 + c];
        }
        if (tid < 96) {
            float inv1 = g1[tid] / sqrtf(v1[tid] + 1e-5f);
            float inv2 = g2[tid] / sqrtf(v2[tid] + 1e-5f);
            g_cb[tid] = mlp_b[tid] * inv1 + b1[tid] - m1[tid] * inv1;
            g_ob[tid] = out_b[tid] * inv2 + b2[tid] - m2[tid] * inv2;
        }
        for (int i = tid; i < 96 * 3 * 26; i += 256) {
            int e = i / 78, c = (i / 26) % 3, v = i % 26;
            float val = 0.f;
            if (v < 25) {
                float acc = mlp_w[e*18 + c];
                #pragma unroll
                for (int s = 2; s <= 5; s++)
                    acc += alph2[s][v] * mlp_w[e*18 + s*3 + c];
                float inv = g1[e] / sqrtf(v1[e] + 1e-5f);
                val = inv * acc;
            }
            g_coef2[e][c][v] = val;
        }
    }
    // heavy part: spread across all 8 blocks
    for (int i = bid * 256 + tid; i < 96 * 96 * 5; i += 8 * 256) {
        int o = i / 480, q = (i / 5) % 96, w = i % 5;
        float inv2 = g2[o] / sqrtf(v2[o] + 1e-5f);
        g_OW2[w][q][o] = inv2 * out_w[i];
    }
}

// ---------------------------------------------------------------------------
// A/B producer: one block per (n, 8 B-frames). 256 threads.
// A: register-blocked f32x2 GEMM W2T[15x96] @ ms[15x208], two 104-col passes.
// B: f32x2 pair sweep (e, v-pair) x 8 frames.
// ---------------------------------------------------------------------------
__global__ __launch_bounds__(256) void kAB(const float* __restrict__ x)
{
    __shared__ __align__(16) float S[9416];
    float* NsS  = S;                // [3200]
    float* W2s  = S + 3200;         // [15][96]
    float* msS  = S + 4640;         // [15][208]
    float* XsS  = S + 7760;         // [3][8][26]
    float* xrS  = S + 8384;         // [3][12][26]
    float* cbs  = S + 9320;         // [96]

    int n  = blockIdx.y;
    int f0 = blockIdx.x * 8;        // B frames f0..f0+7
    int tid = threadIdx.x;

    // ---- stage constants + raw x ----
    {
        const float4* src = (const float4*)g_NmatF;
        float4* dst = (float4*)NsS;
        for (int i = tid; i < 800; i += 256) dst[i] = src[i];
        const float4* src2 = (const float4*)&g_W2T[0][0];
        float4* dst2 = (float4*)W2s;
        for (int i = tid; i < 360; i += 256) dst2[i] = src2[i];
    }
    if (tid < 96) cbs[tid] = g_cb[tid];
    for (int i = tid; i < 936; i += 256) {          // xr[c][fr][v], tau = f0-4+fr
        int c = i / 312, r = i - c * 312;
        int fr = r / 26, v = r - fr * 26;
        int tau = f0 - 4 + fr;
        float val = 0.f;
        if (tau >= 0 && tau < TT && v < 25)
            val = x[((n*3 + c)*TT + tau)*VV + v];
        xrS[i] = val;
    }
    __syncthreads();

    // ---- window sums: Xs[c][j][u], A-frame t = f0-2+j ----
    for (int i = tid; i < 624; i += 256) {
        int c = i / 208, r = i - c * 208;
        int j = r / 26, u = r - j * 26;
        const float* xp = &xrS[(c*12 + j)*26 + u];
        XsS[i] = xp[0] + xp[26] + xp[52] + xp[78] + xp[104];
    }
    __syncthreads();

    // ---- ms[sc][jj*26+v] = sum_u N_s[v][u] * Xs[c][jj][u] ----
    for (int i = tid; i < 3120; i += 256) {
        int sc = i / 208, col = i - sc * 208;
        int s = sc / 3, c = sc - s * 3;
        int j = col / 26, v = col - j * 26;
        const float* Nrow = &NsS[(s*25 + v)*25];
        const float* Xr = &XsS[(c*8 + j)*26];
        float acc = 0.f;
        #pragma unroll
        for (int u = 0; u < 25; u++) acc += Nrow[u] * Xr[u];
        msS[i] = acc;
    }
    __syncthreads();

    // ---- A GEMM: two passes of 104 cols; thread tile 12 o x 4 cols ----
    int og = tid >> 5;      // 0..7
    int cg = tid & 31;      // 0..31, active cg<26
    for (int h = 0; h < 2; h++) {
        if (cg < 26) {
            unsigned long long acc[6][4];
            #pragma unroll
            for (int p = 0; p < 6; p++)
                #pragma unroll
                for (int j = 0; j < 4; j++) acc[p][j] = 0ULL;

            int colb = cg << 2;
            #pragma unroll
            for (int sc = 0; sc < 15; sc++) {
                float4 m4 = *(const float4*)&msS[sc*208 + h*104 + colb];
                unsigned long long hh0 = pack2(m4.x, m4.x);
                unsigned long long hh1 = pack2(m4.y, m4.y);
                unsigned long long hh2 = pack2(m4.z, m4.z);
                unsigned long long hh3 = pack2(m4.w, m4.w);
                const ulonglong2* wp = (const ulonglong2*)&W2s[sc*96 + og*12];
                ulonglong2 wa = wp[0], wb = wp[1], wc = wp[2];
                fma2(acc[0][0], wa.x, hh0); fma2(acc[0][1], wa.x, hh1);
                fma2(acc[0][2], wa.x, hh2); fma2(acc[0][3], wa.x, hh3);
                fma2(acc[1][0], wa.y, hh0); fma2(acc[1][1], wa.y, hh1);
                fma2(acc[1][2], wa.y, hh2); fma2(acc[1][3], wa.y, hh3);
                fma2(acc[2][0], wb.x, hh0); fma2(acc[2][1], wb.x, hh1);
                fma2(acc[2][2], wb.x, hh2); fma2(acc[2][3], wb.x, hh3);
                fma2(acc[3][0], wb.y, hh0); fma2(acc[3][1], wb.y, hh1);
                fma2(acc[3][2], wb.y, hh2); fma2(acc[3][3], wb.y, hh3);
                fma2(acc[4][0], wc.x, hh0); fma2(acc[4][1], wc.x, hh1);
                fma2(acc[4][2], wc.x, hh2); fma2(acc[4][3], wc.x, hh3);
                fma2(acc[5][0], wc.y, hh0); fma2(acc[5][1], wc.y, hh1);
                fma2(acc[5][2], wc.y, hh2); fma2(acc[5][3], wc.y, hh3);
            }

            // epilogue: +cb, vector store into padded g_A
            int t0 = f0 - 2 + 4*h;                       // always even
            int lo = (t0 < 0) ? (-t0) * PC : 0;          // multiple of 4
            int hi = ((TT - t0) < 4 ? (TT - t0) : 4) * PC;
            if (colb >= lo && colb + 4 <= hi) {
                long gc = (long)t0 * PC + colb;
                #pragma unroll
                for (int p = 0; p < 6; p++) {
                    int o = og * 12 + 2 * p;
                    float blo = cbs[o], bhi = cbs[o + 1];
                    float l0,h0_,l1,h1_,l2,h2_,l3,h3_;
                    unpack2(acc[p][0], l0, h0_);
                    unpack2(acc[p][1], l1, h1_);
                    unpack2(acc[p][2], l2, h2_);
                    unpack2(acc[p][3], l3, h3_);
                    *(float4*)&g_A[n][o][gc] =
                        make_float4(l0+blo, l1+blo, l2+blo, l3+blo);
                    *(float4*)&g_A[n][o+1][gc] =
                        make_float4(h0_+bhi, h1_+bhi, h2_+bhi, h3_+bhi);
                }
            }
        }
    }

    // ---- B: (e, v-pair) x 8 frames, f32x2 ----
    for (int i = tid; i < 96 * 13; i += 256) {
        int e = i / 13, vp = i - e * 13;
        int v = vp << 1;
        float2 c0 = *(const float2*)&g_coef2[e][0][v];
        float2 c1 = *(const float2*)&g_coef2[e][1][v];
        float2 c2 = *(const float2*)&g_coef2[e][2][v];
        unsigned long long cc0 = pack2(c0.x, c0.y);
        unsigned long long cc1 = pack2(c1.x, c1.y);
        unsigned long long cc2 = pack2(c2.x, c2.y);
        float* Bo = &g_B[n][e][(long)f0 * PC + v];
        #pragma unroll
        for (int j = 0; j < 8; j++) {
            float2 x0 = *(const float2*)&xrS[((0*12) + j+2)*26 + v];
            float2 x1 = *(const float2*)&xrS[((1*12) + j+2)*26 + v];
            float2 x2 = *(const float2*)&xrS[((2*12) + j+2)*26 + v];
            unsigned long long acc = 0ULL;
            fma2(acc, cc0, pack2(x0.x, x0.y));
            fma2(acc, cc1, pack2(x1.x, x1.y));
            fma2(acc, cc2, pack2(x2.x, x2.y));
            float lo, hi;
            unpack2(acc, lo, hi);
            *(float2*)(Bo + j * PC) = make_float2(lo, hi);
        }
    }
}

// ---------------------------------------------------------------------------
// Output GEMM over padded cols: out = ob + sum_{w,e} OW2[w][e][:]*relu(A+Bsh)
// Block: 96 o x 128 padded cols, 256 threads, thread tile 12 o x 4 cols.
// ---------------------------------------------------------------------------
__global__ __launch_bounds__(256, 2) void kOut(float* __restrict__ out)
{
    extern __shared__ float sm[];
    float* Hs  = sm;                   // [96][128]
    float* OWs = sm + 96*128;          // [96][96]
    float* obs = OWs + 96*96;          // [96]

    int tid = threadIdx.x;
    int n = blockIdx.y;
    int col0 = blockIdx.x * 128;

    if (tid < 96) obs[tid] = g_ob[tid];

    int og = tid >> 5;
    int cg = tid & 31;

    unsigned long long acc[6][4];
    #pragma unroll
    for (int p = 0; p < 6; p++)
        #pragma unroll
        for (int j = 0; j < 4; j++) acc[p][j] = 0ULL;

    const float* Arow = &g_A[n][0][0];
    const float* Brow = &g_B[n][0][0];

    #pragma unroll
    for (int w = 0; w < 5; w++) {
        // stage OW chunk
        const float4* src = (const float4*)&g_OW2[w][0][0];
        float4* dst = (float4*)OWs;
        for (int i = tid; i < (96*96)/4; i += 256) dst[i] = src[i];
        // build H chunk: all-vector loads thanks to 26-padding
        for (int q = tid; q < 96 * 32; q += 256) {
            int e = q >> 5, c4 = (q & 31) << 2;
            int tv = col0 + c4;
            float4 h4;
            if (tv < TVA) {
                float4 a4 = *(const float4*)(Arow + e*TVA + tv);
                const float* bp = Brow + e*TVB + tv + PC*w;
                float4 b4;
                if ((w & 1) == 0) {
                    b4 = *(const float4*)bp;
                } else {
                    float2 blo = *(const float2*)bp;
                    float2 bhi = *(const float2*)(bp + 2);
                    b4 = make_float4(blo.x, blo.y, bhi.x, bhi.y);
                }
                h4.x = fmaxf(a4.x + b4.x, 0.f);
                h4.y = fmaxf(a4.y + b4.y, 0.f);
                h4.z = fmaxf(a4.z + b4.z, 0.f);
                h4.w = fmaxf(a4.w + b4.w, 0.f);
            } else {
                h4 = make_float4(0.f, 0.f, 0.f, 0.f);
            }
            *(float4*)(Hs + (e << 7) + c4) = h4;
        }
        __syncthreads();

        #pragma unroll 2
        for (int e = 0; e < 96; e++) {
            float4 h4 = *(const float4*)(Hs + (e << 7) + (cg << 2));
            unsigned long long hh0 = pack2(h4.x, h4.x);
            unsigned long long hh1 = pack2(h4.y, h4.y);
            unsigned long long hh2 = pack2(h4.z, h4.z);
            unsigned long long hh3 = pack2(h4.w, h4.w);
            const ulonglong2* wp = (const ulonglong2*)(OWs + e*96 + og*12);
            ulonglong2 wa = wp[0], wb = wp[1], wc = wp[2];
            fma2(acc[0][0], wa.x, hh0); fma2(acc[0][1], wa.x, hh1);
            fma2(acc[0][2], wa.x, hh2); fma2(acc[0][3], wa.x, hh3);
            fma2(acc[1][0], wa.y, hh0); fma2(acc[1][1], wa.y, hh1);
            fma2(acc[1][2], wa.y, hh2); fma2(acc[1][3], wa.y, hh3);
            fma2(acc[2][0], wb.x, hh0); fma2(acc[2][1], wb.x, hh1);
            fma2(acc[2][2], wb.x, hh2); fma2(acc[2][3], wb.x, hh3);
            fma2(acc[3][0], wb.y, hh0); fma2(acc[3][1], wb.y, hh1);
            fma2(acc[3][2], wb.y, hh2); fma2(acc[3][3], wb.y, hh3);
            fma2(acc[4][0], wc.x, hh0); fma2(acc[4][1], wc.x, hh1);
            fma2(acc[4][2], wc.x, hh2); fma2(acc[4][3], wc.x, hh3);
            fma2(acc[5][0], wc.y, hh0); fma2(acc[5][1], wc.y, hh1);
            fma2(acc[5][2], wc.y, hh2); fma2(acc[5][3], wc.y, hh3);
        }
        __syncthreads();
    }

    // epilogue: padded col -> compact (t,v) mapping, scalar guarded stores
    int tvb = col0 + (cg << 2);
    int tk[4], vk[4];
    bool ok[4];
    #pragma unroll
    for (int k = 0; k < 4; k++) {
        int c = tvb + k;
        int t = c / PC;
        int v = c - t * PC;
        tk[k] = t; vk[k] = v;
        ok[k] = (c < TVA) && (v < VV);
    }
    #pragma unroll
    for (int p = 0; p < 6; p++) {
        int o = og*12 + p*2;
        float blo = obs[o], bhi = obs[o+1];
        float l[4], hh[4];
        unpack2(acc[p][0], l[0], hh[0]);
        unpack2(acc[p][1], l[1], hh[1]);
        unpack2(acc[p][2], l[2], hh[2]);
        unpack2(acc[p][3], l[3], hh[3]);
        float* o0 = &out[((size_t)(n*96 + o))*OUTTV];
        float* o1 = &out[((size_t)(n*96 + o + 1))*OUTTV];
        #pragma unroll
        for (int k = 0; k < 4; k++) {
            if (ok[k]) {
                int idx = tk[k]*VV + vk[k];
                o0[idx] = l[k] + blo;
                o1[idx] = hh[k] + bhi;
            }
        }
    }
}

// ---------------------------------------------------------------------------
// Launcher
// ---------------------------------------------------------------------------
extern "C" void kernel_launch(void* const* d_in, const int* in_sizes, int n_in,
                              void* d_out, int out_size)
{
    (void)in_sizes; (void)n_in; (void)out_size;
    const float* x     = (const float*)d_in[0];
    const float* mlp_w = (const float*)d_in[1];
    const float* mlp_b = (const float*)d_in[2];
    const float* g1    = (const float*)d_in[3];
    const float* b1    = (const float*)d_in[4];
    const float* m1    = (const float*)d_in[5];
    const float* v1    = (const float*)d_in[6];
    const float* out_w = (const float*)d_in[7];
    const float* out_b = (const float*)d_in[8];
    const float* g2    = (const float*)d_in[9];
    const float* b2    = (const float*)d_in[10];
    const float* m2    = (const float*)d_in[11];
    const float* v2    = (const float*)d_in[12];
    float* out = (float*)d_out;

    const int smem3 = (96*128 + 96*96 + 96) * (int)sizeof(float);  // 86400 B
    cudaFuncSetAttribute(kOut, cudaFuncAttributeMaxDynamicSharedMemorySize, smem3);

    kSetup<<<8, 256>>>(mlp_w, mlp_b, g1, b1, m1, v1, out_w, out_b, g2, b2, m2, v2);
    kAB<<<dim3(NFB / 8, NB), 256>>>(x);                 // 38 x 64
    kOut<<<dim3((TVA + 127) / 128, NB), 256, smem3>>>(out);  // 61 x 64
}

// round 8
// speedup vs baseline: 1.9457x; 1.0564x over previous
#include <cuda_runtime.h>
#include <cuda_bf16.h>
#include <mma.h>
#include <math.h>
#include <stdint.h>

using namespace nvcuda;

// ---------------------------------------------------------------------------
// Problem constants
// ---------------------------------------------------------------------------
#define NB   64
#define TT   300
#define VV   25
#define PC   26                 // padded cols per frame
#define EMB  96
#define TVA  (TT*PC)            // 7800
#define NFB  (TT+4)             // 304
#define TVB  (NFB*PC)           // 7904
#define OUTTV (TT*VV)           // 7500

// smem layout for kOutTC (bytes)
#define OFF_AHI  0              // [96][136] bf16 = 26112
#define OFF_ALO  26112          // [96][136] bf16 = 26112
#define OFF_WHI  52224          // [96][104] bf16 = 19968
#define OFF_WLO  72192          // [96][104] bf16 = 19968  (contiguous after WHI)
#define OFF_OBS  92160          // [96] f32 = 384
#define SMEM_TC  92544
#define LDA      136
#define LDB      104
#define LDD      100            // f32 D staging [128][100] reuses bytes [0,51200)

// ---------------------------------------------------------------------------
// Device-global scratch
// ---------------------------------------------------------------------------
__device__ __align__(16) float g_NmatF[3200];
__device__ __align__(16) float g_W2T[15][96];
__device__ __align__(16) float g_coef2[96][3][26];
__device__ float g_cb[96];
__device__ float g_ob[96];
__device__ __align__(16) __nv_bfloat16 g_Wbf[5][2][96][104];  // [w][hi/lo][o][k=e] col-major B tiles
__device__ __align__(16) float g_A[NB][EMB][TVA];
__device__ __align__(16) float g_B[NB][EMB][TVB];

// ---------------------------------------------------------------------------
// f32x2 helpers
// ---------------------------------------------------------------------------
__device__ __forceinline__ unsigned long long pack2(float a, float b) {
    unsigned long long r;
    asm("mov.b64 %0, {%1, %2};" : "=l"(r) : "f"(a), "f"(b));
    return r;
}
__device__ __forceinline__ void unpack2(unsigned long long v, float& lo, float& hi) {
    asm("mov.b64 {%0, %1}, %2;" : "=f"(lo), "=f"(hi) : "l"(v));
}
__device__ __forceinline__ void fma2(unsigned long long& acc,
                                     unsigned long long a, unsigned long long b) {
    asm("fma.rn.f32x2 %0, %1, %2, %0;" : "+l"(acc) : "l"(a), "l"(b));
}
// pack two f32 -> bf16x2 (a -> low half, b -> high half)
__device__ __forceinline__ uint32_t cvt_bf16x2(float a, float b) {
    uint32_t r;
    asm("cvt.rn.satfinite.bf16x2.f32 %0, %1, %2;" : "=r"(r) : "f"(b), "f"(a));
    return r;
}

// ---------------------------------------------------------------------------
// Setup: graph masks, BN folding, split-bf16 col-major output weights.
// ---------------------------------------------------------------------------
__global__ __launch_bounds__(256) void kSetup(
                       const float* __restrict__ mlp_w, const float* __restrict__ mlp_b,
                       const float* __restrict__ g1, const float* __restrict__ b1,
                       const float* __restrict__ m1, const float* __restrict__ v1,
                       const float* __restrict__ out_w, const float* __restrict__ out_b,
                       const float* __restrict__ g2, const float* __restrict__ b2,
                       const float* __restrict__ m2, const float* __restrict__ v2)
{
    __shared__ unsigned int Brow[25];
    __shared__ unsigned int Sm[6][25];
    __shared__ float alph[6][25];
    __shared__ float alph2[6][25];
    int tid = threadIdx.x;
    int bid = blockIdx.x;

    if (tid < 25) {
        const unsigned char eg[24][2] = {{1,2},{2,21},{3,21},{4,3},{5,21},{6,5},
            {7,6},{8,7},{9,21},{10,9},{11,10},{12,11},{13,1},{14,13},{15,14},
            {16,15},{17,1},{18,17},{19,18},{20,19},{22,23},{23,8},{24,25},{25,12}};
        unsigned int m = 1u << tid;
        #pragma unroll
        for (int k = 0; k < 24; k++) {
            int a = eg[k][0] - 1, b = eg[k][1] - 1;
            if (a == tid) m |= 1u << b;
            if (b == tid) m |= 1u << a;
        }
        Brow[tid] = m;
        Sm[1][tid] = m;
    }
    __syncthreads();
    for (int k = 2; k <= 5; k++) {
        if (tid < 25) {
            unsigned int prev = Sm[k-1][tid], nm = prev;
            for (int u = 0; u < 25; u++)
                if ((prev >> u) & 1) nm |= Brow[u];
            Sm[k][tid] = nm;
        }
        __syncthreads();
    }
    if (tid < 125) {
        int s = tid / 25 + 1, v = tid % 25;
        int r = __popc(Sm[s][v]) - ((s >= 2) ? __popc(Sm[s-1][v]) : 0);
        int deg = 5 * r + ((s == 1) ? 0 : 1);
        alph[s][v]  = (deg > 0) ? 1.0f / sqrtf((float)deg) : 0.f;
        alph2[s][v] = (deg > 0) ? 1.0f / (float)deg : 0.f;
    }
    __syncthreads();

    if (bid == 0) {
        for (int i = tid; i < 3200; i += 256) {
            float val = 0.f;
            if (i < 3125) {
                int s = i / 625 + 1, v = (i / 25) % 25, u = i % 25;
                unsigned int bits = Sm[s][v] & ~((s >= 2) ? Sm[s-1][v] : 0u);
                val = ((bits >> u) & 1) ? alph[s][v] * alph[s][u] : 0.f;
            }
            g_NmatF[i] = val;
        }
        for (int i = tid; i < 96 * 15; i += 256) {
            int e = i / 15, sc = i % 15;
            int s = sc / 3, c = sc % 3;
            float inv = g1[e] / sqrtf(v1[e] + 1e-5f);
            g_W2T[sc][e] = inv * mlp_w[e*18 + (s+1)*3 + c];
        }
        if (tid < 96) {
            float inv1 = g1[tid] / sqrtf(v1[tid] + 1e-5f);
            float inv2 = g2[tid] / sqrtf(v2[tid] + 1e-5f);
            g_cb[tid] = mlp_b[tid] * inv1 + b1[tid] - m1[tid] * inv1;
            g_ob[tid] = out_b[tid] * inv2 + b2[tid] - m2[tid] * inv2;
        }
        for (int i = tid; i < 96 * 3 * 26; i += 256) {
            int e = i / 78, c = (i / 26) % 3, v = i % 26;
            float val = 0.f;
            if (v < 25) {
                float acc = mlp_w[e*18 + c];
                #pragma unroll
                for (int s = 2; s <= 5; s++)
                    acc += alph2[s][v] * mlp_w[e*18 + s*3 + c];
                float inv = g1[e] / sqrtf(v1[e] + 1e-5f);
                val = inv * acc;
            }
            g_coef2[e][c][v] = val;
        }
    }

    // split-bf16 output weights as col-major B tiles: g_Wbf[w][part][o][k=e]
    for (int i = bid * 256 + tid; i < 5 * 2 * 96 * 104; i += 8 * 256) {
        int w = i / (2 * 96 * 104);
        int r = i % (2 * 96 * 104);
        int part = r / (96 * 104);
        int q = r % (96 * 104);
        int o = q / 104, k = q % 104;
        float val = 0.f;
        if (k < 96) {
            float inv2 = g2[o] / sqrtf(v2[o] + 1e-5f);
            val = inv2 * out_w[(o * 96 + k) * 5 + w];
        }
        __nv_bfloat16 h = __float2bfloat16(val);
        if (part == 0)
            g_Wbf[w][0][o][k] = h;
        else
            g_Wbf[w][1][o][k] = __float2bfloat16(val - __bfloat162float(h));
    }
}

// ---------------------------------------------------------------------------
// A/B producer (unchanged from R6 passing version)
// ---------------------------------------------------------------------------
__global__ __launch_bounds__(256) void kAB(const float* __restrict__ x)
{
    __shared__ __align__(16) float S[9416];
    float* NsS  = S;                // [3200]
    float* W2s  = S + 3200;         // [15][96]
    float* msS  = S + 4640;         // [15][208]
    float* XsS  = S + 7760;         // [3][8][26]
    float* xrS  = S + 8384;         // [3][12][26]
    float* cbs  = S + 9320;         // [96]

    int n  = blockIdx.y;
    int f0 = blockIdx.x * 8;
    int tid = threadIdx.x;

    {
        const float4* src = (const float4*)g_NmatF;
        float4* dst = (float4*)NsS;
        for (int i = tid; i < 800; i += 256) dst[i] = src[i];
        const float4* src2 = (const float4*)&g_W2T[0][0];
        float4* dst2 = (float4*)W2s;
        for (int i = tid; i < 360; i += 256) dst2[i] = src2[i];
    }
    if (tid < 96) cbs[tid] = g_cb[tid];
    for (int i = tid; i < 936; i += 256) {
        int c = i / 312, r = i - c * 312;
        int fr = r / 26, v = r - fr * 26;
        int tau = f0 - 4 + fr;
        float val = 0.f;
        if (tau >= 0 && tau < TT && v < 25)
            val = x[((n*3 + c)*TT + tau)*VV + v];
        xrS[i] = val;
    }
    __syncthreads();

    for (int i = tid; i < 624; i += 256) {
        int c = i / 208, r = i - c * 208;
        int j = r / 26, u = r - j * 26;
        const float* xp = &xrS[(c*12 + j)*26 + u];
        XsS[i] = xp[0] + xp[26] + xp[52] + xp[78] + xp[104];
    }
    __syncthreads();

    for (int i = tid; i < 3120; i += 256) {
        int sc = i / 208, col = i - sc * 208;
        int s = sc / 3, c = sc - s * 3;
        int j = col / 26, v = col - j * 26;
        const float* Nrow = &NsS[(s*25 + v)*25];
        const float* Xr = &XsS[(c*8 + j)*26];
        float acc = 0.f;
        #pragma unroll
        for (int u = 0; u < 25; u++) acc += Nrow[u] * Xr[u];
        msS[i] = acc;
    }
    __syncthreads();

    int og = tid >> 5;
    int cg = tid & 31;
    for (int h = 0; h < 2; h++) {
        if (cg < 26) {
            unsigned long long acc[6][4];
            #pragma unroll
            for (int p = 0; p < 6; p++)
                #pragma unroll
                for (int j = 0; j < 4; j++) acc[p][j] = 0ULL;

            int colb = cg << 2;
            #pragma unroll
            for (int sc = 0; sc < 15; sc++) {
                float4 m4 = *(const float4*)&msS[sc*208 + h*104 + colb];
                unsigned long long hh0 = pack2(m4.x, m4.x);
                unsigned long long hh1 = pack2(m4.y, m4.y);
                unsigned long long hh2 = pack2(m4.z, m4.z);
                unsigned long long hh3 = pack2(m4.w, m4.w);
                const ulonglong2* wp = (const ulonglong2*)&W2s[sc*96 + og*12];
                ulonglong2 wa = wp[0], wb = wp[1], wc = wp[2];
                fma2(acc[0][0], wa.x, hh0); fma2(acc[0][1], wa.x, hh1);
                fma2(acc[0][2], wa.x, hh2); fma2(acc[0][3], wa.x, hh3);
                fma2(acc[1][0], wa.y, hh0); fma2(acc[1][1], wa.y, hh1);
                fma2(acc[1][2], wa.y, hh2); fma2(acc[1][3], wa.y, hh3);
                fma2(acc[2][0], wb.x, hh0); fma2(acc[2][1], wb.x, hh1);
                fma2(acc[2][2], wb.x, hh2); fma2(acc[2][3], wb.x, hh3);
                fma2(acc[3][0], wb.y, hh0); fma2(acc[3][1], wb.y, hh1);
                fma2(acc[3][2], wb.y, hh2); fma2(acc[3][3], wb.y, hh3);
                fma2(acc[4][0], wc.x, hh0); fma2(acc[4][1], wc.x, hh1);
                fma2(acc[4][2], wc.x, hh2); fma2(acc[4][3], wc.x, hh3);
                fma2(acc[5][0], wc.y, hh0); fma2(acc[5][1], wc.y, hh1);
                fma2(acc[5][2], wc.y, hh2); fma2(acc[5][3], wc.y, hh3);
            }

            int t0 = f0 - 2 + 4*h;
            int lo = (t0 < 0) ? (-t0) * PC : 0;
            int hi = ((TT - t0) < 4 ? (TT - t0) : 4) * PC;
            if (colb >= lo && colb + 4 <= hi) {
                long gc = (long)t0 * PC + colb;
                #pragma unroll
                for (int p = 0; p < 6; p++) {
                    int o = og * 12 + 2 * p;
                    float blo = cbs[o], bhi = cbs[o + 1];
                    float l0,h0_,l1,h1_,l2,h2_,l3,h3_;
                    unpack2(acc[p][0], l0, h0_);
                    unpack2(acc[p][1], l1, h1_);
                    unpack2(acc[p][2], l2, h2_);
                    unpack2(acc[p][3], l3, h3_);
                    *(float4*)&g_A[n][o][gc] =
                        make_float4(l0+blo, l1+blo, l2+blo, l3+blo);
                    *(float4*)&g_A[n][o+1][gc] =
                        make_float4(h0_+bhi, h1_+bhi, h2_+bhi, h3_+bhi);
                }
            }
        }
    }

    for (int i = tid; i < 96 * 13; i += 256) {
        int e = i / 13, vp = i - e * 13;
        int v = vp << 1;
        float2 c0 = *(const float2*)&g_coef2[e][0][v];
        float2 c1 = *(const float2*)&g_coef2[e][1][v];
        float2 c2 = *(const float2*)&g_coef2[e][2][v];
        unsigned long long cc0 = pack2(c0.x, c0.y);
        unsigned long long cc1 = pack2(c1.x, c1.y);
        unsigned long long cc2 = pack2(c2.x, c2.y);
        float* Bo = &g_B[n][e][(long)f0 * PC + v];
        #pragma unroll
        for (int j = 0; j < 8; j++) {
            float2 x0 = *(const float2*)&xrS[((0*12) + j+2)*26 + v];
            float2 x1 = *(const float2*)&xrS[((1*12) + j+2)*26 + v];
            float2 x2 = *(const float2*)&xrS[((2*12) + j+2)*26 + v];
            unsigned long long acc = 0ULL;
            fma2(acc, cc0, pack2(x0.x, x0.y));
            fma2(acc, cc1, pack2(x1.x, x1.y));
            fma2(acc, cc2, pack2(x2.x, x2.y));
            float lo, hi;
            unpack2(acc, lo, hi);
            *(float2*)(Bo + j * PC) = make_float2(lo, hi);
        }
    }
}

// ---------------------------------------------------------------------------
// Output GEMM via WMMA bf16 (HMMA fallback, no tcgen05).
// Block: D[M=128 cols][N=96 outs], K=96 e; 8 warps, warp tile 32x48.
// Split-bf16: acc += Ahi*Whi + Alo*Whi + Ahi*Wlo, accumulated over w=0..4.
// A stored col-major [e][col] (coalesced smem writes from H-build).
// ---------------------------------------------------------------------------
__global__ __launch_bounds__(256) void kOutTC(float* __restrict__ out)
{
    extern __shared__ char smem[];
    __nv_bfloat16* AhiS = (__nv_bfloat16*)(smem + OFF_AHI);
    __nv_bfloat16* AloS = (__nv_bfloat16*)(smem + OFF_ALO);
    __nv_bfloat16* WhiS = (__nv_bfloat16*)(smem + OFF_WHI);
    __nv_bfloat16* WloS = (__nv_bfloat16*)(smem + OFF_WLO);
    float* obs = (float*)(smem + OFF_OBS);

    int tid = threadIdx.x;
    int n = blockIdx.y;
    int col0 = blockIdx.x * 128;
    int warpid = tid >> 5;
    int m0 = (warpid & 3) * 32;    // col offset of warp tile
    int n0 = (warpid >> 2) * 48;   // out offset of warp tile

    if (tid < 96) obs[tid] = g_ob[tid];

    wmma::fragment<wmma::accumulator, 16, 16, 16, float> acc[2][3];
    #pragma unroll
    for (int i = 0; i < 2; i++)
        #pragma unroll
        for (int j = 0; j < 3; j++)
            wmma::fill_fragment(acc[i][j], 0.0f);

    const float* Arow = &g_A[n][0][0];
    const float* Brow = &g_B[n][0][0];

    for (int w = 0; w < 5; w++) {
        // stage split weights (Whi+Wlo contiguous, 39936 B)
        {
            const uint4* src = (const uint4*)(&g_Wbf[w][0][0][0]);
            uint4* dst = (uint4*)(smem + OFF_WHI);
            #pragma unroll 4
            for (int i = tid; i < 2496; i += 256) dst[i] = src[i];
        }
        // build H = relu(A + B_shift), split to bf16 hi/lo, col-major [e][col]
        for (int i = tid; i < 96 * 64; i += 256) {
            int e = i >> 6, cp = i & 63;
            int col = cp << 1;
            int tv = col0 + col;
            float2 h2 = make_float2(0.f, 0.f);
            if (tv < TVA) {
                float2 a2 = *(const float2*)(Arow + (size_t)e * TVA + tv);
                float2 b2 = *(const float2*)(Brow + (size_t)e * TVB + tv + PC * w);
                h2.x = fmaxf(a2.x + b2.x, 0.f);
                h2.y = fmaxf(a2.y + b2.y, 0.f);
            }
            uint32_t hp = cvt_bf16x2(h2.x, h2.y);
            float f0 = __uint_as_float(hp << 16);
            float f1 = __uint_as_float(hp & 0xFFFF0000u);
            uint32_t lp = cvt_bf16x2(h2.x - f0, h2.y - f1);
            *(uint32_t*)(AhiS + e * LDA + col) = hp;
            *(uint32_t*)(AloS + e * LDA + col) = lp;
        }
        __syncthreads();

        #pragma unroll
        for (int pass = 0; pass < 3; pass++) {
            const __nv_bfloat16* Ap = (pass == 1) ? AloS : AhiS;
            const __nv_bfloat16* Wp = (pass == 2) ? WloS : WhiS;
            #pragma unroll
            for (int kf = 0; kf < 6; kf++) {
                int k0 = kf * 16;
                wmma::fragment<wmma::matrix_a, 16, 16, 16, __nv_bfloat16,
                               wmma::col_major> af0, af1;
                wmma::load_matrix_sync(af0, Ap + k0 * LDA + m0, LDA);
                wmma::load_matrix_sync(af1, Ap + k0 * LDA + m0 + 16, LDA);
                #pragma unroll
                for (int j = 0; j < 3; j++) {
                    wmma::fragment<wmma::matrix_b, 16, 16, 16, __nv_bfloat16,
                                   wmma::col_major> bf;
                    wmma::load_matrix_sync(bf, Wp + (n0 + 16 * j) * LDB + k0, LDB);
                    wmma::mma_sync(acc[0][j], af0, bf, acc[0][j]);
                    wmma::mma_sync(acc[1][j], af1, bf, acc[1][j]);
                }
            }
        }
        __syncthreads();   // before next w overwrites A/W tiles
    }

    // epilogue: stage D to smem (reuses A/W bytes), then compact write-out
    float* Ds = (float*)smem;
    #pragma unroll
    for (int i = 0; i < 2; i++)
        #pragma unroll
        for (int j = 0; j < 3; j++)
            wmma::store_matrix_sync(Ds + (m0 + 16 * i) * LDD + (n0 + 16 * j),
                                    acc[i][j], LDD, wmma::mem_row_major);
    __syncthreads();

    for (int q = tid; q < 96 * 128; q += 256) {
        int o = q >> 7, col = q & 127;
        int tv = col0 + col;
        int t = tv / PC, v = tv - t * PC;
        if (tv < TVA && v < VV) {
            out[((size_t)(n * 96 + o)) * OUTTV + t * VV + v] =
                Ds[col * LDD + o] + obs[o];
        }
    }
}

// ---------------------------------------------------------------------------
// Launcher
// ---------------------------------------------------------------------------
extern "C" void kernel_launch(void* const* d_in, const int* in_sizes, int n_in,
                              void* d_out, int out_size)
{
    (void)in_sizes; (void)n_in; (void)out_size;
    const float* x     = (const float*)d_in[0];
    const float* mlp_w = (const float*)d_in[1];
    const float* mlp_b = (const float*)d_in[2];
    const float* g1    = (const float*)d_in[3];
    const float* b1    = (const float*)d_in[4];
    const float* m1    = (const float*)d_in[5];
    const float* v1    = (const float*)d_in[6];
    const float* out_w = (const float*)d_in[7];
    const float* out_b = (const float*)d_in[8];
    const float* g2    = (const float*)d_in[9];
    const float* b2    = (const float*)d_in[10];
    const float* m2    = (const float*)d_in[11];
    const float* v2    = (const float*)d_in[12];
    float* out = (float*)d_out;

    cudaFuncSetAttribute(kOutTC, cudaFuncAttributeMaxDynamicSharedMemorySize, SMEM_TC);

    kSetup<<<8, 256>>>(mlp_w, mlp_b, g1, b1, m1, v1, out_w, out_b, g2, b2, m2, v2);
    kAB<<<dim3(NFB / 8, NB), 256>>>(x);
    kOutTC<<<dim3((TVA + 127) / 128, NB), 256, SMEM_TC>>>(out);
}

// round 9
// speedup vs baseline: 3.2397x; 1.6650x over previous
#include <cuda_runtime.h>
#include <cuda_bf16.h>
#include <cuda_fp16.h>
#include <mma.h>
#include <math.h>
#include <stdint.h>

using namespace nvcuda;

// ---------------------------------------------------------------------------
// Problem constants
// ---------------------------------------------------------------------------
#define NB   64
#define TT   300
#define VV   25
#define PC   26                 // padded cols per frame
#define EMB  96
#define TVA  (TT*PC)            // 7800
#define NFB  (TT+4)             // 304
#define TVB  (NFB*PC)           // 7904
#define OUTTV (TT*VV)           // 7500

// smem layout for kOutTC (bytes)
#define OFF_AHI  0              // [96][136] fp16 = 26112
#define OFF_ALO  26112          // [96][136] fp16 = 26112
#define OFF_W    52224          // [96][104] fp16 = 19968
#define OFF_OBS  72192          // [96] f32 = 384
#define SMEM_TC  72576
#define LDA      136
#define LDB      104
#define LDD      100            // f32 D staging [128][100] reuses bytes [0,51200)

// ---------------------------------------------------------------------------
// Device-global scratch
// ---------------------------------------------------------------------------
__device__ __align__(16) float g_NmatF[3200];
__device__ __align__(16) float g_W2T[15][96];
__device__ __align__(16) float g_coef2[96][3][26];
__device__ float g_cb[96];
__device__ float g_ob[96];
__device__ __align__(16) __half g_Wh[5][96][104];   // [w][o][k=e] fp16 B tiles (col-major)
__device__ __align__(16) float g_A[NB][EMB][TVA];
__device__ __align__(16) float g_B[NB][EMB][TVB];

// ---------------------------------------------------------------------------
// f32x2 helpers
// ---------------------------------------------------------------------------
__device__ __forceinline__ unsigned long long pack2(float a, float b) {
    unsigned long long r;
    asm("mov.b64 %0, {%1, %2};" : "=l"(r) : "f"(a), "f"(b));
    return r;
}
__device__ __forceinline__ void unpack2(unsigned long long v, float& lo, float& hi) {
    asm("mov.b64 {%0, %1}, %2;" : "=f"(lo), "=f"(hi) : "l"(v));
}
__device__ __forceinline__ void fma2(unsigned long long& acc,
                                     unsigned long long a, unsigned long long b) {
    asm("fma.rn.f32x2 %0, %1, %2, %0;" : "+l"(acc) : "l"(a), "l"(b));
}
__device__ __forceinline__ uint32_t h2_u32(__half2 h) {
    return *reinterpret_cast<uint32_t*>(&h);
}

// ---------------------------------------------------------------------------
// Setup: graph masks, BN folding, fp16 col-major output weights.
// ---------------------------------------------------------------------------
__global__ __launch_bounds__(256) void kSetup(
                       const float* __restrict__ mlp_w, const float* __restrict__ mlp_b,
                       const float* __restrict__ g1, const float* __restrict__ b1,
                       const float* __restrict__ m1, const float* __restrict__ v1,
                       const float* __restrict__ out_w, const float* __restrict__ out_b,
                       const float* __restrict__ g2, const float* __restrict__ b2,
                       const float* __restrict__ m2, const float* __restrict__ v2)
{
    __shared__ unsigned int Brow[25];
    __shared__ unsigned int Sm[6][25];
    __shared__ float alph[6][25];
    __shared__ float alph2[6][25];
    int tid = threadIdx.x;
    int bid = blockIdx.x;

    if (tid < 25) {
        const unsigned char eg[24][2] = {{1,2},{2,21},{3,21},{4,3},{5,21},{6,5},
            {7,6},{8,7},{9,21},{10,9},{11,10},{12,11},{13,1},{14,13},{15,14},
            {16,15},{17,1},{18,17},{19,18},{20,19},{22,23},{23,8},{24,25},{25,12}};
        unsigned int m = 1u << tid;
        #pragma unroll
        for (int k = 0; k < 24; k++) {
            int a = eg[k][0] - 1, b = eg[k][1] - 1;
            if (a == tid) m |= 1u << b;
            if (b == tid) m |= 1u << a;
        }
        Brow[tid] = m;
        Sm[1][tid] = m;
    }
    __syncthreads();
    for (int k = 2; k <= 5; k++) {
        if (tid < 25) {
            unsigned int prev = Sm[k-1][tid], nm = prev;
            for (int u = 0; u < 25; u++)
                if ((prev >> u) & 1) nm |= Brow[u];
            Sm[k][tid] = nm;
        }
        __syncthreads();
    }
    if (tid < 125) {
        int s = tid / 25 + 1, v = tid % 25;
        int r = __popc(Sm[s][v]) - ((s >= 2) ? __popc(Sm[s-1][v]) : 0);
        int deg = 5 * r + ((s == 1) ? 0 : 1);
        alph[s][v]  = (deg > 0) ? 1.0f / sqrtf((float)deg) : 0.f;
        alph2[s][v] = (deg > 0) ? 1.0f / (float)deg : 0.f;
    }
    __syncthreads();

    if (bid == 0) {
        for (int i = tid; i < 3200; i += 256) {
            float val = 0.f;
            if (i < 3125) {
                int s = i / 625 + 1, v = (i / 25) % 25, u = i % 25;
                unsigned int bits = Sm[s][v] & ~((s >= 2) ? Sm[s-1][v] : 0u);
                val = ((bits >> u) & 1) ? alph[s][v] * alph[s][u] : 0.f;
            }
            g_NmatF[i] = val;
        }
        for (int i = tid; i < 96 * 15; i += 256) {
            int e = i / 15, sc = i % 15;
            int s = sc / 3, c = sc % 3;
            float inv = g1[e] / sqrtf(v1[e] + 1e-5f);
            g_W2T[sc][e] = inv * mlp_w[e*18 + (s+1)*3 + c];
        }
        if (tid < 96) {
            float inv1 = g1[tid] / sqrtf(v1[tid] + 1e-5f);
            float inv2 = g2[tid] / sqrtf(v2[tid] + 1e-5f);
            g_cb[tid] = mlp_b[tid] * inv1 + b1[tid] - m1[tid] * inv1;
            g_ob[tid] = out_b[tid] * inv2 + b2[tid] - m2[tid] * inv2;
        }
        for (int i = tid; i < 96 * 3 * 26; i += 256) {
            int e = i / 78, c = (i / 26) % 3, v = i % 26;
            float val = 0.f;
            if (v < 25) {
                float acc = mlp_w[e*18 + c];
                #pragma unroll
                for (int s = 2; s <= 5; s++)
                    acc += alph2[s][v] * mlp_w[e*18 + s*3 + c];
                float inv = g1[e] / sqrtf(v1[e] + 1e-5f);
                val = inv * acc;
            }
            g_coef2[e][c][v] = val;
        }
    }

    // fp16 output weights as col-major B tiles: g_Wh[w][o][k=e]
    for (int i = bid * 256 + tid; i < 5 * 96 * 104; i += 8 * 256) {
        int w = i / (96 * 104);
        int q = i % (96 * 104);
        int o = q / 104, k = q % 104;
        float val = 0.f;
        if (k < 96) {
            float inv2 = g2[o] / sqrtf(v2[o] + 1e-5f);
            val = inv2 * out_w[(o * 96 + k) * 5 + w];
        }
        g_Wh[w][o][k] = __float2half_rn(val);
    }
}

// ---------------------------------------------------------------------------
// A/B producer (unchanged)
// ---------------------------------------------------------------------------
__global__ __launch_bounds__(256) void kAB(const float* __restrict__ x)
{
    __shared__ __align__(16) float S[9416];
    float* NsS  = S;                // [3200]
    float* W2s  = S + 3200;         // [15][96]
    float* msS  = S + 4640;         // [15][208]
    float* XsS  = S + 7760;         // [3][8][26]
    float* xrS  = S + 8384;         // [3][12][26]
    float* cbs  = S + 9320;         // [96]

    int n  = blockIdx.y;
    int f0 = blockIdx.x * 8;
    int tid = threadIdx.x;

    {
        const float4* src = (const float4*)g_NmatF;
        float4* dst = (float4*)NsS;
        for (int i = tid; i < 800; i += 256) dst[i] = src[i];
        const float4* src2 = (const float4*)&g_W2T[0][0];
        float4* dst2 = (float4*)W2s;
        for (int i = tid; i < 360; i += 256) dst2[i] = src2[i];
    }
    if (tid < 96) cbs[tid] = g_cb[tid];
    for (int i = tid; i < 936; i += 256) {
        int c = i / 312, r = i - c * 312;
        int fr = r / 26, v = r - fr * 26;
        int tau = f0 - 4 + fr;
        float val = 0.f;
        if (tau >= 0 && tau < TT && v < 25)
            val = x[((n*3 + c)*TT + tau)*VV + v];
        xrS[i] = val;
    }
    __syncthreads();

    for (int i = tid; i < 624; i += 256) {
        int c = i / 208, r = i - c * 208;
        int j = r / 26, u = r - j * 26;
        const float* xp = &xrS[(c*12 + j)*26 + u];
        XsS[i] = xp[0] + xp[26] + xp[52] + xp[78] + xp[104];
    }
    __syncthreads();

    for (int i = tid; i < 3120; i += 256) {
        int sc = i / 208, col = i - sc * 208;
        int s = sc / 3, c = sc - s * 3;
        int j = col / 26, v = col - j * 26;
        const float* Nrow = &NsS[(s*25 + v)*25];
        const float* Xr = &XsS[(c*8 + j)*26];
        float acc = 0.f;
        #pragma unroll
        for (int u = 0; u < 25; u++) acc += Nrow[u] * Xr[u];
        msS[i] = acc;
    }
    __syncthreads();

    int og = tid >> 5;
    int cg = tid & 31;
    for (int h = 0; h < 2; h++) {
        if (cg < 26) {
            unsigned long long acc[6][4];
            #pragma unroll
            for (int p = 0; p < 6; p++)
                #pragma unroll
                for (int j = 0; j < 4; j++) acc[p][j] = 0ULL;

            int colb = cg << 2;
            #pragma unroll
            for (int sc = 0; sc < 15; sc++) {
                float4 m4 = *(const float4*)&msS[sc*208 + h*104 + colb];
                unsigned long long hh0 = pack2(m4.x, m4.x);
                unsigned long long hh1 = pack2(m4.y, m4.y);
                unsigned long long hh2 = pack2(m4.z, m4.z);
                unsigned long long hh3 = pack2(m4.w, m4.w);
                const ulonglong2* wp = (const ulonglong2*)&W2s[sc*96 + og*12];
                ulonglong2 wa = wp[0], wb = wp[1], wc = wp[2];
                fma2(acc[0][0], wa.x, hh0); fma2(acc[0][1], wa.x, hh1);
                fma2(acc[0][2], wa.x, hh2); fma2(acc[0][3], wa.x, hh3);
                fma2(acc[1][0], wa.y, hh0); fma2(acc[1][1], wa.y, hh1);
                fma2(acc[1][2], wa.y, hh2); fma2(acc[1][3], wa.y, hh3);
                fma2(acc[2][0], wb.x, hh0); fma2(acc[2][1], wb.x, hh1);
                fma2(acc[2][2], wb.x, hh2); fma2(acc[2][3], wb.x, hh3);
                fma2(acc[3][0], wb.y, hh0); fma2(acc[3][1], wb.y, hh1);
                fma2(acc[3][2], wb.y, hh2); fma2(acc[3][3], wb.y, hh3);
                fma2(acc[4][0], wc.x, hh0); fma2(acc[4][1], wc.x, hh1);
                fma2(acc[4][2], wc.x, hh2); fma2(acc[4][3], wc.x, hh3);
                fma2(acc[5][0], wc.y, hh0); fma2(acc[5][1], wc.y, hh1);
                fma2(acc[5][2], wc.y, hh2); fma2(acc[5][3], wc.y, hh3);
            }

            int t0 = f0 - 2 + 4*h;
            int lo = (t0 < 0) ? (-t0) * PC : 0;
            int hi = ((TT - t0) < 4 ? (TT - t0) : 4) * PC;
            if (colb >= lo && colb + 4 <= hi) {
                long gc = (long)t0 * PC + colb;
                #pragma unroll
                for (int p = 0; p < 6; p++) {
                    int o = og * 12 + 2 * p;
                    float blo = cbs[o], bhi = cbs[o + 1];
                    float l0,h0_,l1,h1_,l2,h2_,l3,h3_;
                    unpack2(acc[p][0], l0, h0_);
                    unpack2(acc[p][1], l1, h1_);
                    unpack2(acc[p][2], l2, h2_);
                    unpack2(acc[p][3], l3, h3_);
                    *(float4*)&g_A[n][o][gc] =
                        make_float4(l0+blo, l1+blo, l2+blo, l3+blo);
                    *(float4*)&g_A[n][o+1][gc] =
                        make_float4(h0_+bhi, h1_+bhi, h2_+bhi, h3_+bhi);
                }
            }
        }
    }

    for (int i = tid; i < 96 * 13; i += 256) {
        int e = i / 13, vp = i - e * 13;
        int v = vp << 1;
        float2 c0 = *(const float2*)&g_coef2[e][0][v];
        float2 c1 = *(const float2*)&g_coef2[e][1][v];
        float2 c2 = *(const float2*)&g_coef2[e][2][v];
        unsigned long long cc0 = pack2(c0.x, c0.y);
        unsigned long long cc1 = pack2(c1.x, c1.y);
        unsigned long long cc2 = pack2(c2.x, c2.y);
        float* Bo = &g_B[n][e][(long)f0 * PC + v];
        #pragma unroll
        for (int j = 0; j < 8; j++) {
            float2 x0 = *(const float2*)&xrS[((0*12) + j+2)*26 + v];
            float2 x1 = *(const float2*)&xrS[((1*12) + j+2)*26 + v];
            float2 x2 = *(const float2*)&xrS[((2*12) + j+2)*26 + v];
            unsigned long long acc = 0ULL;
            fma2(acc, cc0, pack2(x0.x, x0.y));
            fma2(acc, cc1, pack2(x1.x, x1.y));
            fma2(acc, cc2, pack2(x2.x, x2.y));
            float lo, hi;
            unpack2(acc, lo, hi);
            *(float2*)(Bo + j * PC) = make_float2(lo, hi);
        }
    }
}

// ---------------------------------------------------------------------------
// Output GEMM via WMMA fp16 (2-product split: Ahi*W + Alo*W).
// Block: D[M=128 cols][N=96 outs], K=96 e per w-tap; 8 warps, tile 32x48.
// __launch_bounds__(256, 2): 2 CTAs/SM for phase overlap.
// ---------------------------------------------------------------------------
__global__ __launch_bounds__(256, 2) void kOutTC(float* __restrict__ out)
{
    extern __shared__ char smem[];
    __half* AhiS = (__half*)(smem + OFF_AHI);
    __half* AloS = (__half*)(smem + OFF_ALO);
    __half* WS   = (__half*)(smem + OFF_W);
    float* obs = (float*)(smem + OFF_OBS);

    int tid = threadIdx.x;
    int n = blockIdx.y;
    int col0 = blockIdx.x * 128;
    int warpid = tid >> 5;
    int m0 = (warpid & 3) * 32;    // col offset of warp tile
    int n0 = (warpid >> 2) * 48;   // out offset of warp tile

    if (tid < 96) obs[tid] = g_ob[tid];

    wmma::fragment<wmma::accumulator, 16, 16, 16, float> acc[2][3];
    #pragma unroll
    for (int i = 0; i < 2; i++)
        #pragma unroll
        for (int j = 0; j < 3; j++)
            wmma::fill_fragment(acc[i][j], 0.0f);

    const float* Arow = &g_A[n][0][0];
    const float* Brow = &g_B[n][0][0];

    for (int w = 0; w < 5; w++) {
        // stage fp16 weights (19968 B = 1248 uint4)
        {
            const uint4* src = (const uint4*)(&g_Wh[w][0][0]);
            uint4* dst = (uint4*)(smem + OFF_W);
            #pragma unroll 5
            for (int i = tid; i < 1248; i += 256) dst[i] = src[i];
        }
        // build H = relu(A + B_shift), split to fp16 hi/lo, layout [e][col]
        for (int i = tid; i < 96 * 32; i += 256) {
            int e = i >> 5, c4 = (i & 31) << 2;
            int tv = col0 + c4;
            float4 h4 = make_float4(0.f, 0.f, 0.f, 0.f);
            if (tv < TVA) {
                float4 a4 = *(const float4*)(Arow + (size_t)e * TVA + tv);
                const float* bp = Brow + (size_t)e * TVB + tv + PC * w;
                float4 b4;
                if ((w & 1) == 0) {
                    b4 = *(const float4*)bp;
                } else {
                    float2 blo2 = *(const float2*)bp;
                    float2 bhi2 = *(const float2*)(bp + 2);
                    b4 = make_float4(blo2.x, blo2.y, bhi2.x, bhi2.y);
                }
                h4.x = fmaxf(a4.x + b4.x, 0.f);
                h4.y = fmaxf(a4.y + b4.y, 0.f);
                h4.z = fmaxf(a4.z + b4.z, 0.f);
                h4.w = fmaxf(a4.w + b4.w, 0.f);
            }
            __half2 hh01 = __floats2half2_rn(h4.x, h4.y);
            __half2 hh23 = __floats2half2_rn(h4.z, h4.w);
            float l0 = h4.x - __half2float(__low2half(hh01));
            float l1 = h4.y - __half2float(__high2half(hh01));
            float l2 = h4.z - __half2float(__low2half(hh23));
            float l3 = h4.w - __half2float(__high2half(hh23));
            __half2 ll01 = __floats2half2_rn(l0, l1);
            __half2 ll23 = __floats2half2_rn(l2, l3);
            *(uint2*)(AhiS + e * LDA + c4) = make_uint2(h2_u32(hh01), h2_u32(hh23));
            *(uint2*)(AloS + e * LDA + c4) = make_uint2(h2_u32(ll01), h2_u32(ll23));
        }
        __syncthreads();

        #pragma unroll
        for (int kf = 0; kf < 6; kf++) {
            int k0 = kf * 16;
            wmma::fragment<wmma::matrix_b, 16, 16, 16, __half,
                           wmma::col_major> bf[3];
            #pragma unroll
            for (int j = 0; j < 3; j++)
                wmma::load_matrix_sync(bf[j], WS + (n0 + 16 * j) * LDB + k0, LDB);
            #pragma unroll
            for (int pass = 0; pass < 2; pass++) {
                const __half* Ap = pass ? AloS : AhiS;
                wmma::fragment<wmma::matrix_a, 16, 16, 16, __half,
                               wmma::col_major> af0, af1;
                wmma::load_matrix_sync(af0, Ap + k0 * LDA + m0, LDA);
                wmma::load_matrix_sync(af1, Ap + k0 * LDA + m0 + 16, LDA);
                #pragma unroll
                for (int j = 0; j < 3; j++) {
                    wmma::mma_sync(acc[0][j], af0, bf[j], acc[0][j]);
                    wmma::mma_sync(acc[1][j], af1, bf[j], acc[1][j]);
                }
            }
        }
        __syncthreads();   // before next w overwrites A/W tiles
    }

    // epilogue: stage D to smem (reuses A bytes [0,51200)), then compact write
    float* Ds = (float*)smem;
    #pragma unroll
    for (int i = 0; i < 2; i++)
        #pragma unroll
        for (int j = 0; j < 3; j++)
            wmma::store_matrix_sync(Ds + (m0 + 16 * i) * LDD + (n0 + 16 * j),
                                    acc[i][j], LDD, wmma::mem_row_major);
    __syncthreads();

    for (int q = tid; q < 96 * 128; q += 256) {
        int o = q >> 7, col = q & 127;
        int tv = col0 + col;
        int t = tv / PC, v = tv - t * PC;
        if (tv < TVA && v < VV) {
            out[((size_t)(n * 96 + o)) * OUTTV + t * VV + v] =
                Ds[col * LDD + o] + obs[o];
        }
    }
}

// ---------------------------------------------------------------------------
// Launcher
// ---------------------------------------------------------------------------
extern "C" void kernel_launch(void* const* d_in, const int* in_sizes, int n_in,
                              void* d_out, int out_size)
{
    (void)in_sizes; (void)n_in; (void)out_size;
    const float* x     = (const float*)d_in[0];
    const float* mlp_w = (const float*)d_in[1];
    const float* mlp_b = (const float*)d_in[2];
    const float* g1    = (const float*)d_in[3];
    const float* b1    = (const float*)d_in[4];
    const float* m1    = (const float*)d_in[5];
    const float* v1    = (const float*)d_in[6];
    const float* out_w = (const float*)d_in[7];
    const float* out_b = (const float*)d_in[8];
    const float* g2    = (const float*)d_in[9];
    const float* b2    = (const float*)d_in[10];
    const float* m2    = (const float*)d_in[11];
    const float* v2    = (const float*)d_in[12];
    float* out = (float*)d_out;

    cudaFuncSetAttribute(kOutTC, cudaFuncAttributeMaxDynamicSharedMemorySize, SMEM_TC);

    kSetup<<<8, 256>>>(mlp_w, mlp_b, g1, b1, m1, v1, out_w, out_b, g2, b2, m2, v2);
    kAB<<<dim3(NFB / 8, NB), 256>>>(x);
    kOutTC<<<dim3((TVA + 127) / 128, NB), 256, SMEM_TC>>>(out);
}

// round 10
// speedup vs baseline: 3.2553x; 1.0048x over previous
#include <cuda_runtime.h>
#include <cuda_bf16.h>
#include <cuda_fp16.h>
#include <mma.h>
#include <math.h>
#include <stdint.h>

using namespace nvcuda;

// ---------------------------------------------------------------------------
// Problem constants
// ---------------------------------------------------------------------------
#define NB   64
#define TT   300
#define VV   25
#define PC   26                 // padded cols per frame
#define EMB  96
#define TVA  (TT*PC)            // 7800
#define NFB  (TT+4)             // 304
#define TVB  (NFB*PC)           // 7904
#define OUTTV (TT*VV)           // 7500

// smem layout for kOutTC (bytes)
#define OFF_AHI  0              // [96][136] fp16 = 26112
#define OFF_ALO  26112          // [96][136] fp16 = 26112
#define OFF_W    52224          // [96][104] fp16 = 19968
#define OFF_OBS  72192          // [96] f32 = 384
#define SMEM_TC  72576
#define LDA      136
#define LDB      104
#define LDD      100            // f32 D staging [128][100] reuses bytes [0,51200)

// ---------------------------------------------------------------------------
// Device-global scratch
// ---------------------------------------------------------------------------
__device__ __align__(16) float g_NmatF[3200];
__device__ __align__(16) float g_W2T[15][96];
__device__ __align__(16) float g_coef2[96][3][26];
__device__ float g_cb[96];
__device__ float g_ob[96];
__device__ __align__(16) __half g_Wh[5][96][104];   // [w][o][k=e] fp16 B tiles (col-major)
__device__ __align__(16) float g_A[NB][EMB][TVA];
__device__ __align__(16) float g_B[NB][EMB][TVB];

// ---------------------------------------------------------------------------
// f32x2 helpers
// ---------------------------------------------------------------------------
__device__ __forceinline__ unsigned long long pack2(float a, float b) {
    unsigned long long r;
    asm("mov.b64 %0, {%1, %2};" : "=l"(r) : "f"(a), "f"(b));
    return r;
}
__device__ __forceinline__ void unpack2(unsigned long long v, float& lo, float& hi) {
    asm("mov.b64 {%0, %1}, %2;" : "=f"(lo), "=f"(hi) : "l"(v));
}
__device__ __forceinline__ void fma2(unsigned long long& acc,
                                     unsigned long long a, unsigned long long b) {
    asm("fma.rn.f32x2 %0, %1, %2, %0;" : "+l"(acc) : "l"(a), "l"(b));
}
__device__ __forceinline__ uint32_t h2_u32(__half2 h) {
    return *reinterpret_cast<uint32_t*>(&h);
}

// ---------------------------------------------------------------------------
// Setup: graph masks, BN folding, fp16 col-major output weights.
// ---------------------------------------------------------------------------
__global__ __launch_bounds__(256) void kSetup(
                       const float* __restrict__ mlp_w, const float* __restrict__ mlp_b,
                       const float* __restrict__ g1, const float* __restrict__ b1,
                       const float* __restrict__ m1, const float* __restrict__ v1,
                       const float* __restrict__ out_w, const float* __restrict__ out_b,
                       const float* __restrict__ g2, const float* __restrict__ b2,
                       const float* __restrict__ m2, const float* __restrict__ v2)
{
    __shared__ unsigned int Brow[25];
    __shared__ unsigned int Sm[6][25];
    __shared__ float alph[6][25];
    __shared__ float alph2[6][25];
    int tid = threadIdx.x;
    int bid = blockIdx.x;

    if (tid < 25) {
        const unsigned char eg[24][2] = {{1,2},{2,21},{3,21},{4,3},{5,21},{6,5},
            {7,6},{8,7},{9,21},{10,9},{11,10},{12,11},{13,1},{14,13},{15,14},
            {16,15},{17,1},{18,17},{19,18},{20,19},{22,23},{23,8},{24,25},{25,12}};
        unsigned int m = 1u << tid;
        #pragma unroll
        for (int k = 0; k < 24; k++) {
            int a = eg[k][0] - 1, b = eg[k][1] - 1;
            if (a == tid) m |= 1u << b;
            if (b == tid) m |= 1u << a;
        }
        Brow[tid] = m;
        Sm[1][tid] = m;
    }
    __syncthreads();
    for (int k = 2; k <= 5; k++) {
        if (tid < 25) {
            unsigned int prev = Sm[k-1][tid], nm = prev;
            for (int u = 0; u < 25; u++)
                if ((prev >> u) & 1) nm |= Brow[u];
            Sm[k][tid] = nm;
        }
        __syncthreads();
    }
    if (tid < 125) {
        int s = tid / 25 + 1, v = tid % 25;
        int r = __popc(Sm[s][v]) - ((s >= 2) ? __popc(Sm[s-1][v]) : 0);
        int deg = 5 * r + ((s == 1) ? 0 : 1);
        alph[s][v]  = (deg > 0) ? 1.0f / sqrtf((float)deg) : 0.f;
        alph2[s][v] = (deg > 0) ? 1.0f / (float)deg : 0.f;
    }
    __syncthreads();

    if (bid == 0) {
        for (int i = tid; i < 3200; i += 256) {
            float val = 0.f;
            if (i < 3125) {
                int s = i / 625 + 1, v = (i / 25) % 25, u = i % 25;
                unsigned int bits = Sm[s][v] & ~((s >= 2) ? Sm[s-1][v] : 0u);
                val = ((bits >> u) & 1) ? alph[s][v] * alph[s][u] : 0.f;
            }
            g_NmatF[i] = val;
        }
        for (int i = tid; i < 96 * 15; i += 256) {
            int e = i / 15, sc = i % 15;
            int s = sc / 3, c = sc % 3;
            float inv = g1[e] / sqrtf(v1[e] + 1e-5f);
            g_W2T[sc][e] = inv * mlp_w[e*18 + (s+1)*3 + c];
        }
        if (tid < 96) {
            float inv1 = g1[tid] / sqrtf(v1[tid] + 1e-5f);
            float inv2 = g2[tid] / sqrtf(v2[tid] + 1e-5f);
            g_cb[tid] = mlp_b[tid] * inv1 + b1[tid] - m1[tid] * inv1;
            g_ob[tid] = out_b[tid] * inv2 + b2[tid] - m2[tid] * inv2;
        }
        for (int i = tid; i < 96 * 3 * 26; i += 256) {
            int e = i / 78, c = (i / 26) % 3, v = i % 26;
            float val = 0.f;
            if (v < 25) {
                float acc = mlp_w[e*18 + c];
                #pragma unroll
                for (int s = 2; s <= 5; s++)
                    acc += alph2[s][v] * mlp_w[e*18 + s*3 + c];
                float inv = g1[e] / sqrtf(v1[e] + 1e-5f);
                val = inv * acc;
            }
            g_coef2[e][c][v] = val;
        }
    }

    // fp16 output weights as col-major B tiles: g_Wh[w][o][k=e]
    for (int i = bid * 256 + tid; i < 5 * 96 * 104; i += 8 * 256) {
        int w = i / (96 * 104);
        int q = i % (96 * 104);
        int o = q / 104, k = q % 104;
        float val = 0.f;
        if (k < 96) {
            float inv2 = g2[o] / sqrtf(v2[o] + 1e-5f);
            val = inv2 * out_w[(o * 96 + k) * 5 + w];
        }
        g_Wh[w][o][k] = __float2half_rn(val);
    }
}

// ---------------------------------------------------------------------------
// A/B producer (unchanged)
// ---------------------------------------------------------------------------
__global__ __launch_bounds__(256) void kAB(const float* __restrict__ x)
{
    __shared__ __align__(16) float S[9416];
    float* NsS  = S;                // [3200]
    float* W2s  = S + 3200;         // [15][96]
    float* msS  = S + 4640;         // [15][208]
    float* XsS  = S + 7760;         // [3][8][26]
    float* xrS  = S + 8384;         // [3][12][26]
    float* cbs  = S + 9320;         // [96]

    int n  = blockIdx.y;
    int f0 = blockIdx.x * 8;
    int tid = threadIdx.x;

    {
        const float4* src = (const float4*)g_NmatF;
        float4* dst = (float4*)NsS;
        for (int i = tid; i < 800; i += 256) dst[i] = src[i];
        const float4* src2 = (const float4*)&g_W2T[0][0];
        float4* dst2 = (float4*)W2s;
        for (int i = tid; i < 360; i += 256) dst2[i] = src2[i];
    }
    if (tid < 96) cbs[tid] = g_cb[tid];
    for (int i = tid; i < 936; i += 256) {
        int c = i / 312, r = i - c * 312;
        int fr = r / 26, v = r - fr * 26;
        int tau = f0 - 4 + fr;
        float val = 0.f;
        if (tau >= 0 && tau < TT && v < 25)
            val = x[((n*3 + c)*TT + tau)*VV + v];
        xrS[i] = val;
    }
    __syncthreads();

    for (int i = tid; i < 624; i += 256) {
        int c = i / 208, r = i - c * 208;
        int j = r / 26, u = r - j * 26;
        const float* xp = &xrS[(c*12 + j)*26 + u];
        XsS[i] = xp[0] + xp[26] + xp[52] + xp[78] + xp[104];
    }
    __syncthreads();

    for (int i = tid; i < 3120; i += 256) {
        int sc = i / 208, col = i - sc * 208;
        int s = sc / 3, c = sc - s * 3;
        int j = col / 26, v = col - j * 26;
        const float* Nrow = &NsS[(s*25 + v)*25];
        const float* Xr = &XsS[(c*8 + j)*26];
        float acc = 0.f;
        #pragma unroll
        for (int u = 0; u < 25; u++) acc += Nrow[u] * Xr[u];
        msS[i] = acc;
    }
    __syncthreads();

    int og = tid >> 5;
    int cg = tid & 31;
    for (int h = 0; h < 2; h++) {
        if (cg < 26) {
            unsigned long long acc[6][4];
            #pragma unroll
            for (int p = 0; p < 6; p++)
                #pragma unroll
                for (int j = 0; j < 4; j++) acc[p][j] = 0ULL;

            int colb = cg << 2;
            #pragma unroll
            for (int sc = 0; sc < 15; sc++) {
                float4 m4 = *(const float4*)&msS[sc*208 + h*104 + colb];
                unsigned long long hh0 = pack2(m4.x, m4.x);
                unsigned long long hh1 = pack2(m4.y, m4.y);
                unsigned long long hh2 = pack2(m4.z, m4.z);
                unsigned long long hh3 = pack2(m4.w, m4.w);
                const ulonglong2* wp = (const ulonglong2*)&W2s[sc*96 + og*12];
                ulonglong2 wa = wp[0], wb = wp[1], wc = wp[2];
                fma2(acc[0][0], wa.x, hh0); fma2(acc[0][1], wa.x, hh1);
                fma2(acc[0][2], wa.x, hh2); fma2(acc[0][3], wa.x, hh3);
                fma2(acc[1][0], wa.y, hh0); fma2(acc[1][1], wa.y, hh1);
                fma2(acc[1][2], wa.y, hh2); fma2(acc[1][3], wa.y, hh3);
                fma2(acc[2][0], wb.x, hh0); fma2(acc[2][1], wb.x, hh1);
                fma2(acc[2][2], wb.x, hh2); fma2(acc[2][3], wb.x, hh3);
                fma2(acc[3][0], wb.y, hh0); fma2(acc[3][1], wb.y, hh1);
                fma2(acc[3][2], wb.y, hh2); fma2(acc[3][3], wb.y, hh3);
                fma2(acc[4][0], wc.x, hh0); fma2(acc[4][1], wc.x, hh1);
                fma2(acc[4][2], wc.x, hh2); fma2(acc[4][3], wc.x, hh3);
                fma2(acc[5][0], wc.y, hh0); fma2(acc[5][1], wc.y, hh1);
                fma2(acc[5][2], wc.y, hh2); fma2(acc[5][3], wc.y, hh3);
            }

            int t0 = f0 - 2 + 4*h;
            int lo = (t0 < 0) ? (-t0) * PC : 0;
            int hi = ((TT - t0) < 4 ? (TT - t0) : 4) * PC;
            if (colb >= lo && colb + 4 <= hi) {
                long gc = (long)t0 * PC + colb;
                #pragma unroll
                for (int p = 0; p < 6; p++) {
                    int o = og * 12 + 2 * p;
                    float blo = cbs[o], bhi = cbs[o + 1];
                    float l0,h0_,l1,h1_,l2,h2_,l3,h3_;
                    unpack2(acc[p][0], l0, h0_);
                    unpack2(acc[p][1], l1, h1_);
                    unpack2(acc[p][2], l2, h2_);
                    unpack2(acc[p][3], l3, h3_);
                    *(float4*)&g_A[n][o][gc] =
                        make_float4(l0+blo, l1+blo, l2+blo, l3+blo);
                    *(float4*)&g_A[n][o+1][gc] =
                        make_float4(h0_+bhi, h1_+bhi, h2_+bhi, h3_+bhi);
                }
            }
        }
    }

    for (int i = tid; i < 96 * 13; i += 256) {
        int e = i / 13, vp = i - e * 13;
        int v = vp << 1;
        float2 c0 = *(const float2*)&g_coef2[e][0][v];
        float2 c1 = *(const float2*)&g_coef2[e][1][v];
        float2 c2 = *(const float2*)&g_coef2[e][2][v];
        unsigned long long cc0 = pack2(c0.x, c0.y);
        unsigned long long cc1 = pack2(c1.x, c1.y);
        unsigned long long cc2 = pack2(c2.x, c2.y);
        float* Bo = &g_B[n][e][(long)f0 * PC + v];
        #pragma unroll
        for (int j = 0; j < 8; j++) {
            float2 x0 = *(const float2*)&xrS[((0*12) + j+2)*26 + v];
            float2 x1 = *(const float2*)&xrS[((1*12) + j+2)*26 + v];
            float2 x2 = *(const float2*)&xrS[((2*12) + j+2)*26 + v];
            unsigned long long acc = 0ULL;
            fma2(acc, cc0, pack2(x0.x, x0.y));
            fma2(acc, cc1, pack2(x1.x, x1.y));
            fma2(acc, cc2, pack2(x2.x, x2.y));
            float lo, hi;
            unpack2(acc, lo, hi);
            *(float2*)(Bo + j * PC) = make_float2(lo, hi);
        }
    }
}

// ---------------------------------------------------------------------------
// Output GEMM via WMMA fp16 (2-product split: Ahi*W + Alo*W).
// Block: D[M=128 cols][N=96 outs], K=96 e per w-tap; 8 warps, tile 32x48.
// __launch_bounds__(256, 2): 2 CTAs/SM for phase overlap.
// ---------------------------------------------------------------------------
__global__ __launch_bounds__(256, 2) void kOutTC(float* __restrict__ out)
{
    extern __shared__ char smem[];
    __half* AhiS = (__half*)(smem + OFF_AHI);
    __half* AloS = (__half*)(smem + OFF_ALO);
    __half* WS   = (__half*)(smem + OFF_W);
    float* obs = (float*)(smem + OFF_OBS);

    int tid = threadIdx.x;
    int n = blockIdx.y;
    int col0 = blockIdx.x * 128;
    int warpid = tid >> 5;
    int m0 = (warpid & 3) * 32;    // col offset of warp tile
    int n0 = (warpid >> 2) * 48;   // out offset of warp tile

    if (tid < 96) obs[tid] = g_ob[tid];

    wmma::fragment<wmma::accumulator, 16, 16, 16, float> acc[2][3];
    #pragma unroll
    for (int i = 0; i < 2; i++)
        #pragma unroll
        for (int j = 0; j < 3; j++)
            wmma::fill_fragment(acc[i][j], 0.0f);

    const float* Arow = &g_A[n][0][0];
    const float* Brow = &g_B[n][0][0];

    for (int w = 0; w < 5; w++) {
        // stage fp16 weights (19968 B = 1248 uint4)
        {
            const uint4* src = (const uint4*)(&g_Wh[w][0][0]);
            uint4* dst = (uint4*)(smem + OFF_W);
            #pragma unroll 5
            for (int i = tid; i < 1248; i += 256) dst[i] = src[i];
        }
        // build H = relu(A + B_shift), split to fp16 hi/lo, layout [e][col]
        for (int i = tid; i < 96 * 32; i += 256) {
            int e = i >> 5, c4 = (i & 31) << 2;
            int tv = col0 + c4;
            float4 h4 = make_float4(0.f, 0.f, 0.f, 0.f);
            if (tv < TVA) {
                float4 a4 = *(const float4*)(Arow + (size_t)e * TVA + tv);
                const float* bp = Brow + (size_t)e * TVB + tv + PC * w;
                float4 b4;
                if ((w & 1) == 0) {
                    b4 = *(const float4*)bp;
                } else {
                    float2 blo2 = *(const float2*)bp;
                    float2 bhi2 = *(const float2*)(bp + 2);
                    b4 = make_float4(blo2.x, blo2.y, bhi2.x, bhi2.y);
                }
                h4.x = fmaxf(a4.x + b4.x, 0.f);
                h4.y = fmaxf(a4.y + b4.y, 0.f);
                h4.z = fmaxf(a4.z + b4.z, 0.f);
                h4.w = fmaxf(a4.w + b4.w, 0.f);
            }
            __half2 hh01 = __floats2half2_rn(h4.x, h4.y);
            __half2 hh23 = __floats2half2_rn(h4.z, h4.w);
            float l0 = h4.x - __half2float(__low2half(hh01));
            float l1 = h4.y - __half2float(__high2half(hh01));
            float l2 = h4.z - __half2float(__low2half(hh23));
            float l3 = h4.w - __half2float(__high2half(hh23));
            __half2 ll01 = __floats2half2_rn(l0, l1);
            __half2 ll23 = __floats2half2_rn(l2, l3);
            *(uint2*)(AhiS + e * LDA + c4) = make_uint2(h2_u32(hh01), h2_u32(hh23));
            *(uint2*)(AloS + e * LDA + c4) = make_uint2(h2_u32(ll01), h2_u32(ll23));
        }
        __syncthreads();

        #pragma unroll
        for (int kf = 0; kf < 6; kf++) {
            int k0 = kf * 16;
            wmma::fragment<wmma::matrix_b, 16, 16, 16, __half,
                           wmma::col_major> bf[3];
            #pragma unroll
            for (int j = 0; j < 3; j++)
                wmma::load_matrix_sync(bf[j], WS + (n0 + 16 * j) * LDB + k0, LDB);
            #pragma unroll
            for (int pass = 0; pass < 2; pass++) {
                const __half* Ap = pass ? AloS : AhiS;
                wmma::fragment<wmma::matrix_a, 16, 16, 16, __half,
                               wmma::col_major> af0, af1;
                wmma::load_matrix_sync(af0, Ap + k0 * LDA + m0, LDA);
                wmma::load_matrix_sync(af1, Ap + k0 * LDA + m0 + 16, LDA);
                #pragma unroll
                for (int j = 0; j < 3; j++) {
                    wmma::mma_sync(acc[0][j], af0, bf[j], acc[0][j]);
                    wmma::mma_sync(acc[1][j], af1, bf[j], acc[1][j]);
                }
            }
        }
        __syncthreads();   // before next w overwrites A/W tiles
    }

    // epilogue: stage D to smem (reuses A bytes [0,51200)), then compact write
    float* Ds = (float*)smem;
    #pragma unroll
    for (int i = 0; i < 2; i++)
        #pragma unroll
        for (int j = 0; j < 3; j++)
            wmma::store_matrix_sync(Ds + (m0 + 16 * i) * LDD + (n0 + 16 * j),
                                    acc[i][j], LDD, wmma::mem_row_major);
    __syncthreads();

    for (int q = tid; q < 96 * 128; q += 256) {
        int o = q >> 7, col = q & 127;
        int tv = col0 + col;
        int t = tv / PC, v = tv - t * PC;
        if (tv < TVA && v < VV) {
            out[((size_t)(n * 96 + o)) * OUTTV + t * VV + v] =
                Ds[col * LDD + o] + obs[o];
        }
    }
}

// ---------------------------------------------------------------------------
// Launcher
// ---------------------------------------------------------------------------
extern "C" void kernel_launch(void* const* d_in, const int* in_sizes, int n_in,
                              void* d_out, int out_size)
{
    (void)in_sizes; (void)n_in; (void)out_size;
    const float* x     = (const float*)d_in[0];
    const float* mlp_w = (const float*)d_in[1];
    const float* mlp_b = (const float*)d_in[2];
    const float* g1    = (const float*)d_in[3];
    const float* b1    = (const float*)d_in[4];
    const float* m1    = (const float*)d_in[5];
    const float* v1    = (const float*)d_in[6];
    const float* out_w = (const float*)d_in[7];
    const float* out_b = (const float*)d_in[8];
    const float* g2    = (const float*)d_in[9];
    const float* b2    = (const float*)d_in[10];
    const float* m2    = (const float*)d_in[11];
    const float* v2    = (const float*)d_in[12];
    float* out = (float*)d_out;

    cudaFuncSetAttribute(kOutTC, cudaFuncAttributeMaxDynamicSharedMemorySize, SMEM_TC);

    kSetup<<<8, 256>>>(mlp_w, mlp_b, g1, b1, m1, v1, out_w, out_b, g2, b2, m2, v2);
    kAB<<<dim3(NFB / 8, NB), 256>>>(x);
    kOutTC<<<dim3((TVA + 127) / 128, NB), 256, SMEM_TC>>>(out);
}

// round 11
// speedup vs baseline: 3.5304x; 1.0845x over previous
#include <cuda_runtime.h>
#include <cuda_bf16.h>
#include <cuda_fp16.h>
#include <mma.h>
#include <math.h>
#include <stdint.h>

using namespace nvcuda;

// ---------------------------------------------------------------------------
// Problem constants
// ---------------------------------------------------------------------------
#define NB   64
#define TT   300
#define VV   25
#define PC   26                 // padded cols per frame
#define EMB  96
#define TVA  (TT*PC)            // 7800
#define NFB  (TT+4)             // 304
#define TVB  (NFB*PC)           // 7904
#define OUTTV (TT*VV)           // 7500

// smem layout for kOutTC (bytes)
#define OFF_AHI  0              // [96][136] fp16 = 26112
#define OFF_W    26112          // [96][104] fp16 = 19968
#define OFF_OBS  51200          // [96] f32 (placed after D staging region)
#define SMEM_TC  51584
#define LDA      136
#define LDB      104
#define LDD      100            // f32 D staging [128][100] = 51200 B at offset 0

// ---------------------------------------------------------------------------
// Device-global scratch
// ---------------------------------------------------------------------------
__device__ __align__(16) float g_NmatF[3600];        // [s][v][28] padded rows
__device__ __align__(16) float g_W2T[15][96];
__device__ __align__(16) float g_coef2[96][3][26];
__device__ float g_cb[96];
__device__ float g_ob[96];
__device__ __align__(16) __half g_Wh[5][96][104];    // [w][o][k=e] fp16 B tiles
__device__ __align__(16) float g_A[NB][EMB][TVA];
__device__ __align__(16) float g_B[NB][EMB][TVB];

// ---------------------------------------------------------------------------
// f32x2 helpers
// ---------------------------------------------------------------------------
__device__ __forceinline__ unsigned long long pack2(float a, float b) {
    unsigned long long r;
    asm("mov.b64 %0, {%1, %2};" : "=l"(r) : "f"(a), "f"(b));
    return r;
}
__device__ __forceinline__ void unpack2(unsigned long long v, float& lo, float& hi) {
    asm("mov.b64 {%0, %1}, %2;" : "=f"(lo), "=f"(hi) : "l"(v));
}
__device__ __forceinline__ void fma2(unsigned long long& acc,
                                     unsigned long long a, unsigned long long b) {
    asm("fma.rn.f32x2 %0, %1, %2, %0;" : "+l"(acc) : "l"(a), "l"(b));
}
__device__ __forceinline__ uint32_t h2_u32(__half2 h) {
    return *reinterpret_cast<uint32_t*>(&h);
}

// ---------------------------------------------------------------------------
// Setup: graph masks, BN folding, fp16 col-major output weights.
// ---------------------------------------------------------------------------
__global__ __launch_bounds__(256) void kSetup(
                       const float* __restrict__ mlp_w, const float* __restrict__ mlp_b,
                       const float* __restrict__ g1, const float* __restrict__ b1,
                       const float* __restrict__ m1, const float* __restrict__ v1,
                       const float* __restrict__ out_w, const float* __restrict__ out_b,
                       const float* __restrict__ g2, const float* __restrict__ b2,
                       const float* __restrict__ m2, const float* __restrict__ v2)
{
    __shared__ unsigned int Brow[25];
    __shared__ unsigned int Sm[6][25];
    __shared__ float alph[6][25];
    __shared__ float alph2[6][25];
    int tid = threadIdx.x;
    int bid = blockIdx.x;

    if (tid < 25) {
        const unsigned char eg[24][2] = {{1,2},{2,21},{3,21},{4,3},{5,21},{6,5},
            {7,6},{8,7},{9,21},{10,9},{11,10},{12,11},{13,1},{14,13},{15,14},
            {16,15},{17,1},{18,17},{19,18},{20,19},{22,23},{23,8},{24,25},{25,12}};
        unsigned int m = 1u << tid;
        #pragma unroll
        for (int k = 0; k < 24; k++) {
            int a = eg[k][0] - 1, b = eg[k][1] - 1;
            if (a == tid) m |= 1u << b;
            if (b == tid) m |= 1u << a;
        }
        Brow[tid] = m;
        Sm[1][tid] = m;
    }
    __syncthreads();
    for (int k = 2; k <= 5; k++) {
        if (tid < 25) {
            unsigned int prev = Sm[k-1][tid], nm = prev;
            for (int u = 0; u < 25; u++)
                if ((prev >> u) & 1) nm |= Brow[u];
            Sm[k][tid] = nm;
        }
        __syncthreads();
    }
    if (tid < 125) {
        int s = tid / 25 + 1, v = tid % 25;
        int r = __popc(Sm[s][v]) - ((s >= 2) ? __popc(Sm[s-1][v]) : 0);
        int deg = 5 * r + ((s == 1) ? 0 : 1);
        alph[s][v]  = (deg > 0) ? 1.0f / sqrtf((float)deg) : 0.f;
        alph2[s][v] = (deg > 0) ? 1.0f / (float)deg : 0.f;
    }
    __syncthreads();

    if (bid == 0) {
        // padded hop matrices: [s0][v][28], rows zero beyond u=24
        for (int i = tid; i < 3600; i += 256) {
            float val = 0.f;
            if (i < 3500) {
                int s0 = i / 700, r = i % 700, v = r / 28, u = r % 28;
                if (u < 25) {
                    unsigned int bits = Sm[s0+1][v] & ~((s0 >= 1) ? Sm[s0][v] : 0u);
                    val = ((bits >> u) & 1) ? alph[s0+1][v] * alph[s0+1][u] : 0.f;
                }
            }
            g_NmatF[i] = val;
        }
        for (int i = tid; i < 96 * 15; i += 256) {
            int e = i / 15, sc = i % 15;
            int s = sc / 3, c = sc % 3;
            float inv = g1[e] / sqrtf(v1[e] + 1e-5f);
            g_W2T[sc][e] = inv * mlp_w[e*18 + (s+1)*3 + c];
        }
        if (tid < 96) {
            float inv1 = g1[tid] / sqrtf(v1[tid] + 1e-5f);
            float inv2 = g2[tid] / sqrtf(v2[tid] + 1e-5f);
            g_cb[tid] = mlp_b[tid] * inv1 + b1[tid] - m1[tid] * inv1;
            g_ob[tid] = out_b[tid] * inv2 + b2[tid] - m2[tid] * inv2;
        }
        for (int i = tid; i < 96 * 3 * 26; i += 256) {
            int e = i / 78, c = (i / 26) % 3, v = i % 26;
            float val = 0.f;
            if (v < 25) {
                float acc = mlp_w[e*18 + c];
                #pragma unroll
                for (int s = 2; s <= 5; s++)
                    acc += alph2[s][v] * mlp_w[e*18 + s*3 + c];
                float inv = g1[e] / sqrtf(v1[e] + 1e-5f);
                val = inv * acc;
            }
            g_coef2[e][c][v] = val;
        }
    }

    // fp16 output weights as col-major B tiles: g_Wh[w][o][k=e]
    for (int i = bid * 256 + tid; i < 5 * 96 * 104; i += 8 * 256) {
        int w = i / (96 * 104);
        int q = i % (96 * 104);
        int o = q / 104, k = q % 104;
        float val = 0.f;
        if (k < 96) {
            float inv2 = g2[o] / sqrtf(v2[o] + 1e-5f);
            val = inv2 * out_w[(o * 96 + k) * 5 + w];
        }
        g_Wh[w][o][k] = __float2half_rn(val);
    }
}

// ---------------------------------------------------------------------------
// A/B producer. ms inner loop vectorized via 28-padded rows (float4 x 7).
// ---------------------------------------------------------------------------
__global__ __launch_bounds__(256) void kAB(const float* __restrict__ x)
{
    __shared__ __align__(16) float S[9864];
    float* NsS  = S;                // [3600]  = [s][v][28]
    float* W2s  = S + 3600;         // [15][96]
    float* msS  = S + 5040;         // [15][208]
    float* XsS  = S + 8160;         // [3][8][28]
    float* xrS  = S + 8832;         // [3][12][26]
    float* cbs  = S + 9768;         // [96]

    int n  = blockIdx.y;
    int f0 = blockIdx.x * 8;
    int tid = threadIdx.x;

    {
        const float4* src = (const float4*)g_NmatF;
        float4* dst = (float4*)NsS;
        for (int i = tid; i < 900; i += 256) dst[i] = src[i];
        const float4* src2 = (const float4*)&g_W2T[0][0];
        float4* dst2 = (float4*)W2s;
        for (int i = tid; i < 360; i += 256) dst2[i] = src2[i];
    }
    if (tid < 96) cbs[tid] = g_cb[tid];
    for (int i = tid; i < 936; i += 256) {
        int c = i / 312, r = i - c * 312;
        int fr = r / 26, v = r - fr * 26;
        int tau = f0 - 4 + fr;
        float val = 0.f;
        if (tau >= 0 && tau < TT && v < 25)
            val = x[((n*3 + c)*TT + tau)*VV + v];
        xrS[i] = val;
    }
    __syncthreads();

    // window sums, 28-padded rows
    for (int i = tid; i < 672; i += 256) {
        int c = i / 224, r = i - c * 224;
        int j = r / 28, u = r - j * 28;
        float s = 0.f;
        if (u < 25) {
            const float* xp = &xrS[(c*12 + j)*26 + u];
            s = xp[0] + xp[26] + xp[52] + xp[78] + xp[104];
        }
        XsS[i] = s;
    }
    __syncthreads();

    // ms[sc][col] = N_s[v][:] . Xs[c][j][:]   (vectorized, 7 x float4)
    for (int i = tid; i < 3120; i += 256) {
        int sc = i / 208, col = i - sc * 208;
        int s = sc / 3, c = sc - s * 3;
        int j = col / 26, v = col - j * 26;
        float acc = 0.f;
        if (v < 25) {
            const float* Nrow = &NsS[(s*25 + v)*28];
            const float* Xr = &XsS[(c*8 + j)*28];
            #pragma unroll
            for (int q = 0; q < 7; q++) {
                float4 nv = *(const float4*)(Nrow + q*4);
                float4 xv = *(const float4*)(Xr + q*4);
                acc += nv.x*xv.x + nv.y*xv.y + nv.z*xv.z + nv.w*xv.w;
            }
        }
        msS[i] = acc;
    }
    __syncthreads();

    int og = tid >> 5;
    int cg = tid & 31;
    for (int h = 0; h < 2; h++) {
        if (cg < 26) {
            unsigned long long acc[6][4];
            #pragma unroll
            for (int p = 0; p < 6; p++)
                #pragma unroll
                for (int j = 0; j < 4; j++) acc[p][j] = 0ULL;

            int colb = cg << 2;
            #pragma unroll
            for (int sc = 0; sc < 15; sc++) {
                float4 m4 = *(const float4*)&msS[sc*208 + h*104 + colb];
                unsigned long long hh0 = pack2(m4.x, m4.x);
                unsigned long long hh1 = pack2(m4.y, m4.y);
                unsigned long long hh2 = pack2(m4.z, m4.z);
                unsigned long long hh3 = pack2(m4.w, m4.w);
                const ulonglong2* wp = (const ulonglong2*)&W2s[sc*96 + og*12];
                ulonglong2 wa = wp[0], wb = wp[1], wc = wp[2];
                fma2(acc[0][0], wa.x, hh0); fma2(acc[0][1], wa.x, hh1);
                fma2(acc[0][2], wa.x, hh2); fma2(acc[0][3], wa.x, hh3);
                fma2(acc[1][0], wa.y, hh0); fma2(acc[1][1], wa.y, hh1);
                fma2(acc[1][2], wa.y, hh2); fma2(acc[1][3], wa.y, hh3);
                fma2(acc[2][0], wb.x, hh0); fma2(acc[2][1], wb.x, hh1);
                fma2(acc[2][2], wb.x, hh2); fma2(acc[2][3], wb.x, hh3);
                fma2(acc[3][0], wb.y, hh0); fma2(acc[3][1], wb.y, hh1);
                fma2(acc[3][2], wb.y, hh2); fma2(acc[3][3], wb.y, hh3);
                fma2(acc[4][0], wc.x, hh0); fma2(acc[4][1], wc.x, hh1);
                fma2(acc[4][2], wc.x, hh2); fma2(acc[4][3], wc.x, hh3);
                fma2(acc[5][0], wc.y, hh0); fma2(acc[5][1], wc.y, hh1);
                fma2(acc[5][2], wc.y, hh2); fma2(acc[5][3], wc.y, hh3);
            }

            int t0 = f0 - 2 + 4*h;
            int lo = (t0 < 0) ? (-t0) * PC : 0;
            int hi = ((TT - t0) < 4 ? (TT - t0) : 4) * PC;
            if (colb >= lo && colb + 4 <= hi) {
                long gc = (long)t0 * PC + colb;
                #pragma unroll
                for (int p = 0; p < 6; p++) {
                    int o = og * 12 + 2 * p;
                    float blo = cbs[o], bhi = cbs[o + 1];
                    float l0,h0_,l1,h1_,l2,h2_,l3,h3_;
                    unpack2(acc[p][0], l0, h0_);
                    unpack2(acc[p][1], l1, h1_);
                    unpack2(acc[p][2], l2, h2_);
                    unpack2(acc[p][3], l3, h3_);
                    *(float4*)&g_A[n][o][gc] =
                        make_float4(l0+blo, l1+blo, l2+blo, l3+blo);
                    *(float4*)&g_A[n][o+1][gc] =
                        make_float4(h0_+bhi, h1_+bhi, h2_+bhi, h3_+bhi);
                }
            }
        }
    }

    for (int i = tid; i < 96 * 13; i += 256) {
        int e = i / 13, vp = i - e * 13;
        int v = vp << 1;
        float2 c0 = *(const float2*)&g_coef2[e][0][v];
        float2 c1 = *(const float2*)&g_coef2[e][1][v];
        float2 c2 = *(const float2*)&g_coef2[e][2][v];
        unsigned long long cc0 = pack2(c0.x, c0.y);
        unsigned long long cc1 = pack2(c1.x, c1.y);
        unsigned long long cc2 = pack2(c2.x, c2.y);
        float* Bo = &g_B[n][e][(long)f0 * PC + v];
        #pragma unroll
        for (int j = 0; j < 8; j++) {
            float2 x0 = *(const float2*)&xrS[((0*12) + j+2)*26 + v];
            float2 x1 = *(const float2*)&xrS[((1*12) + j+2)*26 + v];
            float2 x2 = *(const float2*)&xrS[((2*12) + j+2)*26 + v];
            unsigned long long acc = 0ULL;
            fma2(acc, cc0, pack2(x0.x, x0.y));
            fma2(acc, cc1, pack2(x1.x, x1.y));
            fma2(acc, cc2, pack2(x2.x, x2.y));
            float lo, hi;
            unpack2(acc, lo, hi);
            *(float2*)(Bo + j * PC) = make_float2(lo, hi);
        }
    }
}

// ---------------------------------------------------------------------------
// Output GEMM via WMMA fp16, single product (H rounded to fp16).
// Block: D[M=128 cols][N=96 outs], K=96 e per w-tap; 8 warps, tile 32x48.
// ---------------------------------------------------------------------------
__global__ __launch_bounds__(256, 2) void kOutTC(float* __restrict__ out)
{
    extern __shared__ char smem[];
    __half* AhiS = (__half*)(smem + OFF_AHI);
    __half* WS   = (__half*)(smem + OFF_W);
    float* obs = (float*)(smem + OFF_OBS);

    int tid = threadIdx.x;
    int n = blockIdx.y;
    int col0 = blockIdx.x * 128;
    int warpid = tid >> 5;
    int m0 = (warpid & 3) * 32;    // col offset of warp tile
    int n0 = (warpid >> 2) * 48;   // out offset of warp tile

    if (tid < 96) obs[tid] = g_ob[tid];

    wmma::fragment<wmma::accumulator, 16, 16, 16, float> acc[2][3];
    #pragma unroll
    for (int i = 0; i < 2; i++)
        #pragma unroll
        for (int j = 0; j < 3; j++)
            wmma::fill_fragment(acc[i][j], 0.0f);

    const float* Arow = &g_A[n][0][0];
    const float* Brow = &g_B[n][0][0];

    for (int w = 0; w < 5; w++) {
        // stage fp16 weights (19968 B = 1248 uint4)
        {
            const uint4* src = (const uint4*)(&g_Wh[w][0][0]);
            uint4* dst = (uint4*)(smem + OFF_W);
            #pragma unroll 5
            for (int i = tid; i < 1248; i += 256) dst[i] = src[i];
        }
        // build H = relu(A + B_shift), round to fp16, layout [e][col]
        for (int i = tid; i < 96 * 32; i += 256) {
            int e = i >> 5, c4 = (i & 31) << 2;
            int tv = col0 + c4;
            float4 h4 = make_float4(0.f, 0.f, 0.f, 0.f);
            if (tv < TVA) {
                float4 a4 = *(const float4*)(Arow + (size_t)e * TVA + tv);
                const float* bp = Brow + (size_t)e * TVB + tv + PC * w;
                float4 b4;
                if ((w & 1) == 0) {
                    b4 = *(const float4*)bp;
                } else {
                    float2 blo2 = *(const float2*)bp;
                    float2 bhi2 = *(const float2*)(bp + 2);
                    b4 = make_float4(blo2.x, blo2.y, bhi2.x, bhi2.y);
                }
                h4.x = fmaxf(a4.x + b4.x, 0.f);
                h4.y = fmaxf(a4.y + b4.y, 0.f);
                h4.z = fmaxf(a4.z + b4.z, 0.f);
                h4.w = fmaxf(a4.w + b4.w, 0.f);
            }
            __half2 hh01 = __floats2half2_rn(h4.x, h4.y);
            __half2 hh23 = __floats2half2_rn(h4.z, h4.w);
            *(uint2*)(AhiS + e * LDA + c4) = make_uint2(h2_u32(hh01), h2_u32(hh23));
        }
        __syncthreads();

        #pragma unroll
        for (int kf = 0; kf < 6; kf++) {
            int k0 = kf * 16;
            wmma::fragment<wmma::matrix_b, 16, 16, 16, __half,
                           wmma::col_major> bf[3];
            #pragma unroll
            for (int j = 0; j < 3; j++)
                wmma::load_matrix_sync(bf[j], WS + (n0 + 16 * j) * LDB + k0, LDB);
            wmma::fragment<wmma::matrix_a, 16, 16, 16, __half,
                           wmma::col_major> af0, af1;
            wmma::load_matrix_sync(af0, AhiS + k0 * LDA + m0, LDA);
            wmma::load_matrix_sync(af1, AhiS + k0 * LDA + m0 + 16, LDA);
            #pragma unroll
            for (int j = 0; j < 3; j++) {
                wmma::mma_sync(acc[0][j], af0, bf[j], acc[0][j]);
                wmma::mma_sync(acc[1][j], af1, bf[j], acc[1][j]);
            }
        }
        __syncthreads();   // before next w overwrites A/W tiles
    }

    // epilogue: stage D to smem (reuses A/W bytes [0,51200)), compact write
    float* Ds = (float*)smem;
    #pragma unroll
    for (int i = 0; i < 2; i++)
        #pragma unroll
        for (int j = 0; j < 3; j++)
            wmma::store_matrix_sync(Ds + (m0 + 16 * i) * LDD + (n0 + 16 * j),
                                    acc[i][j], LDD, wmma::mem_row_major);
    __syncthreads();

    for (int q = tid; q < 96 * 128; q += 256) {
        int o = q >> 7, col = q & 127;
        int tv = col0 + col;
        int t = tv / PC, v = tv - t * PC;
        if (tv < TVA && v < VV) {
            out[((size_t)(n * 96 + o)) * OUTTV + t * VV + v] =
                Ds[col * LDD + o] + obs[o];
        }
    }
}

// ---------------------------------------------------------------------------
// Launcher
// ---------------------------------------------------------------------------
extern "C" void kernel_launch(void* const* d_in, const int* in_sizes, int n_in,
                              void* d_out, int out_size)
{
    (void)in_sizes; (void)n_in; (void)out_size;
    const float* x     = (const float*)d_in[0];
    const float* mlp_w = (const float*)d_in[1];
    const float* mlp_b = (const float*)d_in[2];
    const float* g1    = (const float*)d_in[3];
    const float* b1    = (const float*)d_in[4];
    const float* m1    = (const float*)d_in[5];
    const float* v1    = (const float*)d_in[6];
    const float* out_w = (const float*)d_in[7];
    const float* out_b = (const float*)d_in[8];
    const float* g2    = (const float*)d_in[9];
    const float* b2    = (const float*)d_in[10];
    const float* m2    = (const float*)d_in[11];
    const float* v2    = (const float*)d_in[12];
    float* out = (float*)d_out;

    cudaFuncSetAttribute(kOutTC, cudaFuncAttributeMaxDynamicSharedMemorySize, SMEM_TC);

    kSetup<<<8, 256>>>(mlp_w, mlp_b, g1, b1, m1, v1, out_w, out_b, g2, b2, m2, v2);
    kAB<<<dim3(NFB / 8, NB), 256>>>(x);
    kOutTC<<<dim3((TVA + 127) / 128, NB), 256, SMEM_TC>>>(out);
}

// round 12
// speedup vs baseline: 4.0970x; 1.1605x over previous
#include <cuda_runtime.h>
#include <cuda_bf16.h>
#include <cuda_fp16.h>
#include <mma.h>
#include <math.h>
#include <stdint.h>

using namespace nvcuda;

// ---------------------------------------------------------------------------
// Problem constants
// ---------------------------------------------------------------------------
#define NB   64
#define TT   300
#define VV   25
#define PC   26                 // padded cols per frame
#define EMB  96
#define TVA  (TT*PC)            // 7800
#define NFB  (TT+4)             // 304
#define TVB  (NFB*PC)           // 7904
#define TVB2 7912               // B row stride (halves), pad for uint4 tile loads
#define OUTTV (TT*VV)           // 7500

// smem layout for kOutTC (bytes)
#define LDA      136
#define LDBS     232            // B tile width in halves (128 + 4*26)
#define OFF_H    0              // [96][136] fp16 = 26112
#define OFF_B    26112          // [96][232] fp16 = 44544
#define OFF_OBS  70656          // [96] f32 = 384
#define SMEM_TC  71040
#define LDD      100            // f32 D staging [128][100] = 51200 B at offset 0

// ---------------------------------------------------------------------------
// Device-global scratch
// ---------------------------------------------------------------------------
__device__ __align__(16) float g_NmatF[3600];        // [s][v][28] padded rows
__device__ __align__(16) float g_W2T[15][96];
__device__ __align__(16) float g_coef2[96][3][26];
__device__ float g_cb[96];
__device__ float g_ob[96];
__device__ __align__(16) __half g_Wh[5][96][104];    // [w][o][k=e] fp16 B tiles
__device__ __align__(16) __half g_Ah[NB][EMB][TVA];  // A + cb, fp16
__device__ __align__(16) __half g_Bh[NB][EMB][TVB2]; // B, fp16, frame-haloed

// ---------------------------------------------------------------------------
// f32x2 helpers
// ---------------------------------------------------------------------------
__device__ __forceinline__ unsigned long long pack2(float a, float b) {
    unsigned long long r;
    asm("mov.b64 %0, {%1, %2};" : "=l"(r) : "f"(a), "f"(b));
    return r;
}
__device__ __forceinline__ void unpack2(unsigned long long v, float& lo, float& hi) {
    asm("mov.b64 {%0, %1}, %2;" : "=f"(lo), "=f"(hi) : "l"(v));
}
__device__ __forceinline__ void fma2(unsigned long long& acc,
                                     unsigned long long a, unsigned long long b) {
    asm("fma.rn.f32x2 %0, %1, %2, %0;" : "+l"(acc) : "l"(a), "l"(b));
}
__device__ __forceinline__ uint32_t h2_u32(__half2 h) {
    return *reinterpret_cast<uint32_t*>(&h);
}
__device__ __forceinline__ __half2 u32_h2(uint32_t u) {
    return *reinterpret_cast<__half2*>(&u);
}

// ---------------------------------------------------------------------------
// Setup: graph masks, BN folding, fp16 col-major output weights.
// ---------------------------------------------------------------------------
__global__ __launch_bounds__(256) void kSetup(
                       const float* __restrict__ mlp_w, const float* __restrict__ mlp_b,
                       const float* __restrict__ g1, const float* __restrict__ b1,
                       const float* __restrict__ m1, const float* __restrict__ v1,
                       const float* __restrict__ out_w, const float* __restrict__ out_b,
                       const float* __restrict__ g2, const float* __restrict__ b2,
                       const float* __restrict__ m2, const float* __restrict__ v2)
{
    __shared__ unsigned int Brow[25];
    __shared__ unsigned int Sm[6][25];
    __shared__ float alph[6][25];
    __shared__ float alph2[6][25];
    int tid = threadIdx.x;
    int bid = blockIdx.x;

    if (tid < 25) {
        const unsigned char eg[24][2] = {{1,2},{2,21},{3,21},{4,3},{5,21},{6,5},
            {7,6},{8,7},{9,21},{10,9},{11,10},{12,11},{13,1},{14,13},{15,14},
            {16,15},{17,1},{18,17},{19,18},{20,19},{22,23},{23,8},{24,25},{25,12}};
        unsigned int m = 1u << tid;
        #pragma unroll
        for (int k = 0; k < 24; k++) {
            int a = eg[k][0] - 1, b = eg[k][1] - 1;
            if (a == tid) m |= 1u << b;
            if (b == tid) m |= 1u << a;
        }
        Brow[tid] = m;
        Sm[1][tid] = m;
    }
    __syncthreads();
    for (int k = 2; k <= 5; k++) {
        if (tid < 25) {
            unsigned int prev = Sm[k-1][tid], nm = prev;
            for (int u = 0; u < 25; u++)
                if ((prev >> u) & 1) nm |= Brow[u];
            Sm[k][tid] = nm;
        }
        __syncthreads();
    }
    if (tid < 125) {
        int s = tid / 25 + 1, v = tid % 25;
        int r = __popc(Sm[s][v]) - ((s >= 2) ? __popc(Sm[s-1][v]) : 0);
        int deg = 5 * r + ((s == 1) ? 0 : 1);
        alph[s][v]  = (deg > 0) ? 1.0f / sqrtf((float)deg) : 0.f;
        alph2[s][v] = (deg > 0) ? 1.0f / (float)deg : 0.f;
    }
    __syncthreads();

    if (bid == 0) {
        for (int i = tid; i < 3600; i += 256) {
            float val = 0.f;
            if (i < 3500) {
                int s0 = i / 700, r = i % 700, v = r / 28, u = r % 28;
                if (u < 25) {
                    unsigned int bits = Sm[s0+1][v] & ~((s0 >= 1) ? Sm[s0][v] : 0u);
                    val = ((bits >> u) & 1) ? alph[s0+1][v] * alph[s0+1][u] : 0.f;
                }
            }
            g_NmatF[i] = val;
        }
        for (int i = tid; i < 96 * 15; i += 256) {
            int e = i / 15, sc = i % 15;
            int s = sc / 3, c = sc % 3;
            float inv = g1[e] / sqrtf(v1[e] + 1e-5f);
            g_W2T[sc][e] = inv * mlp_w[e*18 + (s+1)*3 + c];
        }
        if (tid < 96) {
            float inv1 = g1[tid] / sqrtf(v1[tid] + 1e-5f);
            float inv2 = g2[tid] / sqrtf(v2[tid] + 1e-5f);
            g_cb[tid] = mlp_b[tid] * inv1 + b1[tid] - m1[tid] * inv1;
            g_ob[tid] = out_b[tid] * inv2 + b2[tid] - m2[tid] * inv2;
        }
        for (int i = tid; i < 96 * 3 * 26; i += 256) {
            int e = i / 78, c = (i / 26) % 3, v = i % 26;
            float val = 0.f;
            if (v < 25) {
                float acc = mlp_w[e*18 + c];
                #pragma unroll
                for (int s = 2; s <= 5; s++)
                    acc += alph2[s][v] * mlp_w[e*18 + s*3 + c];
                float inv = g1[e] / sqrtf(v1[e] + 1e-5f);
                val = inv * acc;
            }
            g_coef2[e][c][v] = val;
        }
    }

    // fp16 output weights as col-major B tiles: g_Wh[w][o][k=e]
    for (int i = bid * 256 + tid; i < 5 * 96 * 104; i += 8 * 256) {
        int w = i / (96 * 104);
        int q = i % (96 * 104);
        int o = q / 104, k = q % 104;
        float val = 0.f;
        if (k < 96) {
            float inv2 = g2[o] / sqrtf(v2[o] + 1e-5f);
            val = inv2 * out_w[(o * 96 + k) * 5 + w];
        }
        g_Wh[w][o][k] = __float2half_rn(val);
    }
}

// ---------------------------------------------------------------------------
// A/B producer; outputs fp16 A (+cb folded) and fp16 B.
// ---------------------------------------------------------------------------
__global__ __launch_bounds__(256) void kAB(const float* __restrict__ x)
{
    __shared__ __align__(16) float S[9864];
    float* NsS  = S;                // [3600]  = [s][v][28]
    float* W2s  = S + 3600;         // [15][96]
    float* msS  = S + 5040;         // [15][208]
    float* XsS  = S + 8160;         // [3][8][28]
    float* xrS  = S + 8832;         // [3][12][26]
    float* cbs  = S + 9768;         // [96]

    int n  = blockIdx.y;
    int f0 = blockIdx.x * 8;
    int tid = threadIdx.x;

    {
        const float4* src = (const float4*)g_NmatF;
        float4* dst = (float4*)NsS;
        for (int i = tid; i < 900; i += 256) dst[i] = src[i];
        const float4* src2 = (const float4*)&g_W2T[0][0];
        float4* dst2 = (float4*)W2s;
        for (int i = tid; i < 360; i += 256) dst2[i] = src2[i];
    }
    if (tid < 96) cbs[tid] = g_cb[tid];
    for (int i = tid; i < 936; i += 256) {
        int c = i / 312, r = i - c * 312;
        int fr = r / 26, v = r - fr * 26;
        int tau = f0 - 4 + fr;
        float val = 0.f;
        if (tau >= 0 && tau < TT && v < 25)
            val = x[((n*3 + c)*TT + tau)*VV + v];
        xrS[i] = val;
    }
    __syncthreads();

    for (int i = tid; i < 672; i += 256) {
        int c = i / 224, r = i - c * 224;
        int j = r / 28, u = r - j * 28;
        float s = 0.f;
        if (u < 25) {
            const float* xp = &xrS[(c*12 + j)*26 + u];
            s = xp[0] + xp[26] + xp[52] + xp[78] + xp[104];
        }
        XsS[i] = s;
    }
    __syncthreads();

    for (int i = tid; i < 3120; i += 256) {
        int sc = i / 208, col = i - sc * 208;
        int s = sc / 3, c = sc - s * 3;
        int j = col / 26, v = col - j * 26;
        float acc = 0.f;
        if (v < 25) {
            const float* Nrow = &NsS[(s*25 + v)*28];
            const float* Xr = &XsS[(c*8 + j)*28];
            #pragma unroll
            for (int q = 0; q < 7; q++) {
                float4 nv = *(const float4*)(Nrow + q*4);
                float4 xv = *(const float4*)(Xr + q*4);
                acc += nv.x*xv.x + nv.y*xv.y + nv.z*xv.z + nv.w*xv.w;
            }
        }
        msS[i] = acc;
    }
    __syncthreads();

    int og = tid >> 5;
    int cg = tid & 31;
    for (int h = 0; h < 2; h++) {
        if (cg < 26) {
            unsigned long long acc[6][4];
            #pragma unroll
            for (int p = 0; p < 6; p++)
                #pragma unroll
                for (int j = 0; j < 4; j++) acc[p][j] = 0ULL;

            int colb = cg << 2;
            #pragma unroll
            for (int sc = 0; sc < 15; sc++) {
                float4 m4 = *(const float4*)&msS[sc*208 + h*104 + colb];
                unsigned long long hh0 = pack2(m4.x, m4.x);
                unsigned long long hh1 = pack2(m4.y, m4.y);
                unsigned long long hh2 = pack2(m4.z, m4.z);
                unsigned long long hh3 = pack2(m4.w, m4.w);
                const ulonglong2* wp = (const ulonglong2*)&W2s[sc*96 + og*12];
                ulonglong2 wa = wp[0], wb = wp[1], wc = wp[2];
                fma2(acc[0][0], wa.x, hh0); fma2(acc[0][1], wa.x, hh1);
                fma2(acc[0][2], wa.x, hh2); fma2(acc[0][3], wa.x, hh3);
                fma2(acc[1][0], wa.y, hh0); fma2(acc[1][1], wa.y, hh1);
                fma2(acc[1][2], wa.y, hh2); fma2(acc[1][3], wa.y, hh3);
                fma2(acc[2][0], wb.x, hh0); fma2(acc[2][1], wb.x, hh1);
                fma2(acc[2][2], wb.x, hh2); fma2(acc[2][3], wb.x, hh3);
                fma2(acc[3][0], wb.y, hh0); fma2(acc[3][1], wb.y, hh1);
                fma2(acc[3][2], wb.y, hh2); fma2(acc[3][3], wb.y, hh3);
                fma2(acc[4][0], wc.x, hh0); fma2(acc[4][1], wc.x, hh1);
                fma2(acc[4][2], wc.x, hh2); fma2(acc[4][3], wc.x, hh3);
                fma2(acc[5][0], wc.y, hh0); fma2(acc[5][1], wc.y, hh1);
                fma2(acc[5][2], wc.y, hh2); fma2(acc[5][3], wc.y, hh3);
            }

            int t0 = f0 - 2 + 4*h;
            int lo = (t0 < 0) ? (-t0) * PC : 0;
            int hi = ((TT - t0) < 4 ? (TT - t0) : 4) * PC;
            if (colb >= lo && colb + 4 <= hi) {
                long gc = (long)t0 * PC + colb;
                #pragma unroll
                for (int p = 0; p < 6; p++) {
                    int o = og * 12 + 2 * p;
                    float blo = cbs[o], bhi = cbs[o + 1];
                    float l0,h0_,l1,h1_,l2,h2_,l3,h3_;
                    unpack2(acc[p][0], l0, h0_);
                    unpack2(acc[p][1], l1, h1_);
                    unpack2(acc[p][2], l2, h2_);
                    unpack2(acc[p][3], l3, h3_);
                    __half2 a01 = __floats2half2_rn(l0+blo, l1+blo);
                    __half2 a23 = __floats2half2_rn(l2+blo, l3+blo);
                    __half2 b01 = __floats2half2_rn(h0_+bhi, h1_+bhi);
                    __half2 b23 = __floats2half2_rn(h2_+bhi, h3_+bhi);
                    *(uint2*)&g_Ah[n][o][gc]   = make_uint2(h2_u32(a01), h2_u32(a23));
                    *(uint2*)&g_Ah[n][o+1][gc] = make_uint2(h2_u32(b01), h2_u32(b23));
                }
            }
        }
    }

    for (int i = tid; i < 96 * 13; i += 256) {
        int e = i / 13, vp = i - e * 13;
        int v = vp << 1;
        float2 c0 = *(const float2*)&g_coef2[e][0][v];
        float2 c1 = *(const float2*)&g_coef2[e][1][v];
        float2 c2 = *(const float2*)&g_coef2[e][2][v];
        unsigned long long cc0 = pack2(c0.x, c0.y);
        unsigned long long cc1 = pack2(c1.x, c1.y);
        unsigned long long cc2 = pack2(c2.x, c2.y);
        __half* Bo = &g_Bh[n][e][(long)f0 * PC + v];
        #pragma unroll
        for (int j = 0; j < 8; j++) {
            float2 x0 = *(const float2*)&xrS[((0*12) + j+2)*26 + v];
            float2 x1 = *(const float2*)&xrS[((1*12) + j+2)*26 + v];
            float2 x2 = *(const float2*)&xrS[((2*12) + j+2)*26 + v];
            unsigned long long acc = 0ULL;
            fma2(acc, cc0, pack2(x0.x, x0.y));
            fma2(acc, cc1, pack2(x1.x, x1.y));
            fma2(acc, cc2, pack2(x2.x, x2.y));
            float lo, hi;
            unpack2(acc, lo, hi);
            *(uint32_t*)(Bo + j * PC) = h2_u32(__floats2half2_rn(lo, hi));
        }
    }
}

// ---------------------------------------------------------------------------
// Output GEMM via WMMA fp16, read-once tiling:
// A tile cached in registers (all 5 w), B tile in smem once (shift span 232),
// W fragments loaded directly from global (L2-resident).
// ---------------------------------------------------------------------------
__global__ __launch_bounds__(256, 2) void kOutTC(float* __restrict__ out)
{
    extern __shared__ char smem[];
    __half* Hs = (__half*)(smem + OFF_H);
    __half* Bs = (__half*)(smem + OFF_B);
    float* obs = (float*)(smem + OFF_OBS);

    int tid = threadIdx.x;
    int n = blockIdx.y;
    int col0 = blockIdx.x * 128;
    int warpid = tid >> 5;
    int m0 = (warpid & 3) * 32;    // col offset of warp tile
    int n0 = (warpid >> 2) * 48;   // out offset of warp tile

    if (tid < 96) obs[tid] = g_ob[tid];

    // B tile: rows e=0..95, cols [col0, col0+232)  (halo covers all 5 shifts)
    for (int i = tid; i < 96 * 29; i += 256) {
        int e = i / 29, q = i - e * 29;
        *(uint4*)(Bs + e * LDBS + q * 8) =
            *(const uint4*)(&g_Bh[n][e][col0 + q * 8]);
    }

    // A tile into registers: thread k-th chunk = (e = i>>5, c4 = (i&31)*4)
    uint2 Areg[12];
    #pragma unroll
    for (int k = 0; k < 12; k++) {
        int i = tid + k * 256;
        int e = i >> 5, c4 = (i & 31) << 2;
        int tv = col0 + c4;
        Areg[k] = (tv < TVA) ? *(const uint2*)(&g_Ah[n][e][tv])
                             : make_uint2(0u, 0u);
    }

    wmma::fragment<wmma::accumulator, 16, 16, 16, float> acc[2][3];
    #pragma unroll
    for (int i = 0; i < 2; i++)
        #pragma unroll
        for (int j = 0; j < 3; j++)
            wmma::fill_fragment(acc[i][j], 0.0f);

    __syncthreads();

    const __half2 z2 = __floats2half2_rn(0.f, 0.f);

    for (int w = 0; w < 5; w++) {
        // build H = relu(A + B_shift) in fp16
        #pragma unroll
        for (int k = 0; k < 12; k++) {
            int i = tid + k * 256;
            int e = i >> 5, c4 = (i & 31) << 2;
            int tv = col0 + c4;
            __half2 h01 = z2, h23 = z2;
            if (tv < TVA) {
                __half2 a01 = u32_h2(Areg[k].x);
                __half2 a23 = u32_h2(Areg[k].y);
                const __half* bp = Bs + e * LDBS + c4 + PC * w;
                __half2 b01 = *(const __half2*)bp;
                __half2 b23 = *(const __half2*)(bp + 2);
                h01 = __hmax2(__hadd2(a01, b01), z2);
                h23 = __hmax2(__hadd2(a23, b23), z2);
            }
            *(uint2*)(Hs + e * LDA + c4) = make_uint2(h2_u32(h01), h2_u32(h23));
        }
        __syncthreads();

        const __half* Wg = &g_Wh[w][0][0];
        #pragma unroll
        for (int kf = 0; kf < 6; kf++) {
            int k0 = kf * 16;
            wmma::fragment<wmma::matrix_b, 16, 16, 16, __half,
                           wmma::col_major> bf[3];
            #pragma unroll
            for (int j = 0; j < 3; j++)
                wmma::load_matrix_sync(bf[j], Wg + (n0 + 16 * j) * 104 + k0, 104);
            wmma::fragment<wmma::matrix_a, 16, 16, 16, __half,
                           wmma::col_major> af0, af1;
            wmma::load_matrix_sync(af0, Hs + k0 * LDA + m0, LDA);
            wmma::load_matrix_sync(af1, Hs + k0 * LDA + m0 + 16, LDA);
            #pragma unroll
            for (int j = 0; j < 3; j++) {
                wmma::mma_sync(acc[0][j], af0, bf[j], acc[0][j]);
                wmma::mma_sync(acc[1][j], af1, bf[j], acc[1][j]);
            }
        }
        __syncthreads();   // before next w overwrites H
    }

    // epilogue: stage D to smem (reuses H/B bytes [0,51200)), compact write
    float* Ds = (float*)smem;
    #pragma unroll
    for (int i = 0; i < 2; i++)
        #pragma unroll
        for (int j = 0; j < 3; j++)
            wmma::store_matrix_sync(Ds + (m0 + 16 * i) * LDD + (n0 + 16 * j),
                                    acc[i][j], LDD, wmma::mem_row_major);
    __syncthreads();

    for (int q = tid; q < 96 * 128; q += 256) {
        int o = q >> 7, col = q & 127;
        int tv = col0 + col;
        int t = tv / PC, v = tv - t * PC;
        if (tv < TVA && v < VV) {
            out[((size_t)(n * 96 + o)) * OUTTV + t * VV + v] =
                Ds[col * LDD + o] + obs[o];
        }
    }
}

// ---------------------------------------------------------------------------
// Launcher
// ---------------------------------------------------------------------------
extern "C" void kernel_launch(void* const* d_in, const int* in_sizes, int n_in,
                              void* d_out, int out_size)
{
    (void)in_sizes; (void)n_in; (void)out_size;
    const float* x     = (const float*)d_in[0];
    const float* mlp_w = (const float*)d_in[1];
    const float* mlp_b = (const float*)d_in[2];
    const float* g1    = (const float*)d_in[3];
    const float* b1    = (const float*)d_in[4];
    const float* m1    = (const float*)d_in[5];
    const float* v1    = (const float*)d_in[6];
    const float* out_w = (const float*)d_in[7];
    const float* out_b = (const float*)d_in[8];
    const float* g2    = (const float*)d_in[9];
    const float* b2    = (const float*)d_in[10];
    const float* m2    = (const float*)d_in[11];
    const float* v2    = (const float*)d_in[12];
    float* out = (float*)d_out;

    cudaFuncSetAttribute(kOutTC, cudaFuncAttributeMaxDynamicSharedMemorySize, SMEM_TC);

    kSetup<<<8, 256>>>(mlp_w, mlp_b, g1, b1, m1, v1, out_w, out_b, g2, b2, m2, v2);
    kAB<<<dim3(NFB / 8, NB), 256>>>(x);
    kOutTC<<<dim3((TVA + 127) / 128, NB), 256, SMEM_TC>>>(out);
}